// round 1
// baseline (speedup 1.0000x reference)
#include <cuda_runtime.h>
#include <math.h>

// ---------------------------------------------------------------------------
// Problem constants
//   T=30, B=1024, D_POSE=135, H=512, K_CODES=512
// Activation layout everywhere: [b, position, channel] (channel contiguous).
// With that layout every conv / convT / linear is a plain row-major GEMM.
// ---------------------------------------------------------------------------

#define EPSV 1e-5f

// ---- scratch buffer (single __device__ global, partitioned by offsets) ----
constexpr long O_X0  = 0;                              // 30720 x 512 (b,t,c)
constexpr long O_E1  = O_X0  + 30720L * 512;           //  6144 x 512
constexpr long O_E2  = O_E1  +  6144L * 512;           //  2048 x 512
constexpr long O_Z   = O_E2  +  2048L * 512;           //  1024 x 512
constexpr long O_Q   = O_Z   +  1024L * 512;           //  1024 x 512 (quantized)
constexpr long O_D0  = O_Q   +  1024L * 512;           //  1024 x 512
constexpr long O_D1  = O_D0  +  1024L * 512;           //  1024 x 1024 (= 2048x512)
constexpr long O_D2  = O_D1  +  2048L * 512;           //  2048 x 1536 (= 6144x512)
constexpr long O_D3  = O_D2  +  6144L * 512;           //  6144 x 2560 (=30720x512)
constexpr long O_WE1 = O_D3  + 30720L * 512;           //  2560 x 512
constexpr long O_WE2 = O_WE1 +  2560L * 512;           //  1536 x 512
constexpr long O_WE3 = O_WE2 +  1536L * 512;           //  1024 x 512
constexpr long O_WD1 = O_WE3 +  1024L * 512;           //   512 x 1024
constexpr long O_WD2 = O_WD1 +   512L * 1024;          //   512 x 1536
constexpr long O_WD3 = O_WD2 +   512L * 1536;          //   512 x 2560
constexpr long O_CBT = O_WD3 +   512L * 2560;          //   512 x 512 (codebook^T)
constexpr long O_SC  = O_CBT +   512L * 512;           //  1024 x 512 (z . c_k)
constexpr long O_CN  = O_SC  +  1024L * 512;           //   512 codebook norms
constexpr long O_SUM = O_CN  + 512;
constexpr long O_SSQ = O_SUM + 512;
constexpr long O_MEAN= O_SSQ + 512;
constexpr long O_ISTD= O_MEAN + 512;
constexpr long O_LOSS= O_ISTD + 512;                   // [0] used
constexpr long O_CNT = O_LOSS + 512;                   // 512 ints (reinterpret)
constexpr long TOTALF= O_CNT + 512;

__device__ float g_buf[TOTALF];

// ---------------------------------------------------------------------------
// Generic fp32 GEMM: C[M,N] = A[M,K] * B[K,N] (+bias).
// 64x64 tile, BK=16, 256 threads, 4x4 micro-tile per thread, float4 smem reads.
// perm==1 : output row remap for the input GEMM (row r=(t*1024+b) -> b*30+t).
// ---------------------------------------------------------------------------
__global__ __launch_bounds__(256)
void gemm_kernel(const float* __restrict__ A, const float* __restrict__ B,
                 const float* __restrict__ bias, float* __restrict__ C,
                 int M, int N, int K, int perm)
{
    __shared__ __align__(16) float As[16][68];
    __shared__ __align__(16) float Bs[16][64];

    const int tid = threadIdx.x;
    const int tx  = tid & 15;
    const int ty  = tid >> 4;
    const int m0  = blockIdx.y * 64;
    const int n0  = blockIdx.x * 64;

    const int arow = tid >> 2;          // 0..63
    const int ak   = (tid & 3) * 4;     // 0,4,8,12
    const int bk   = tid >> 4;          // 0..15
    const int bcol = (tid & 15) * 4;    // 0..60

    float acc[4][4] = {};

    for (int k0 = 0; k0 < K; k0 += 16) {
        // load A tile (64 x 16), store transposed
        {
            const int gm = m0 + arow;
            #pragma unroll
            for (int j = 0; j < 4; j++) {
                const int gk = k0 + ak + j;
                float v = 0.0f;
                if (gm < M && gk < K) v = A[(long)gm * K + gk];
                As[ak + j][arow] = v;
            }
        }
        // load B tile (16 x 64)
        {
            const int gk = k0 + bk;
            #pragma unroll
            for (int j = 0; j < 4; j++) {
                const int gn = n0 + bcol + j;
                float v = 0.0f;
                if (gk < K && gn < N) v = B[(long)gk * N + gn];
                Bs[bk][bcol + j] = v;
            }
        }
        __syncthreads();

        #pragma unroll
        for (int kk = 0; kk < 16; kk++) {
            float av[4], bv[4];
            *(float4*)av = *(const float4*)&As[kk][ty * 4];
            *(float4*)bv = *(const float4*)&Bs[kk][tx * 4];
            #pragma unroll
            for (int i = 0; i < 4; i++)
                #pragma unroll
                for (int j = 0; j < 4; j++)
                    acc[i][j] = fmaf(av[i], bv[j], acc[i][j]);
        }
        __syncthreads();
    }

    #pragma unroll
    for (int i = 0; i < 4; i++) {
        const int gm = m0 + ty * 4 + i;
        if (gm >= M) continue;
        const int orow = perm ? ((gm & 1023) * 30 + (gm >> 10)) : gm;
        #pragma unroll
        for (int j = 0; j < 4; j++) {
            const int gn = n0 + tx * 4 + j;
            if (gn >= N) continue;
            float v = acc[i][j];
            if (bias) v += bias[gn];
            C[(long)orow * N + gn] = v;
        }
    }
}

// ---------------------------------------------------------------------------
// Weight re-layout kernels (run every launch; tiny).
// encoder: wt[(k*I+i)*O + o] = w[o, i, k]   (w shape O,I,Kk)
// decoder: wt[i*(Kk*O) + k*O + o] = w[i, o, k]  (w shape I,O,Kk)
// ---------------------------------------------------------------------------
__global__ void wt_enc(const float* __restrict__ w, float* __restrict__ wt,
                       int I, int O, int Kk)
{
    const int n = I * O * Kk;
    for (int j = blockIdx.x * blockDim.x + threadIdx.x; j < n;
         j += gridDim.x * blockDim.x) {
        const int o = j % O;
        const int rest = j / O;       // k*I + i
        const int i = rest % I;
        const int k = rest / I;
        wt[j] = w[(long)o * I * Kk + (long)i * Kk + k];
    }
}

__global__ void wt_dec(const float* __restrict__ w, float* __restrict__ wt,
                       int I, int O, int Kk)
{
    const int n = I * O * Kk;
    for (int j = blockIdx.x * blockDim.x + threadIdx.x; j < n;
         j += gridDim.x * blockDim.x) {
        const int o = j % O;
        const int rest = j / O;       // i*Kk + k
        const int k = rest % Kk;
        const int i = rest / Kk;
        wt[j] = w[(long)i * O * Kk + (long)o * Kk + k];
    }
}

// codebook transpose + per-code squared norm
__global__ void cb_prep(const float* __restrict__ cb, float* __restrict__ cbT,
                        float* __restrict__ cnorm)
{
    const int k = blockIdx.x;       // code index, 512 blocks x 128 threads
    float s = 0.0f;
    for (int d = threadIdx.x; d < 512; d += 128) {
        const float v = cb[k * 512 + d];
        s += v * v;
        cbT[d * 512 + k] = v;
    }
    __shared__ float sh[128];
    sh[threadIdx.x] = s;
    __syncthreads();
    for (int st = 64; st > 0; st >>= 1) {
        if (threadIdx.x < st) sh[threadIdx.x] += sh[threadIdx.x + st];
        __syncthreads();
    }
    if (threadIdx.x == 0) cnorm[k] = sh[0];
}

// ---------------------------------------------------------------------------
// BatchNorm(+ReLU): per-channel stats over M rows of an [M,512] buffer.
// ---------------------------------------------------------------------------
__global__ void zero_stats(float* a, float* b)
{
    const int i = blockIdx.x * blockDim.x + threadIdx.x;
    if (i < 512) { a[i] = 0.0f; b[i] = 0.0f; }
}

__global__ void bn_stats(const float* __restrict__ X, int M,
                         float* __restrict__ gsum, float* __restrict__ gssq)
{
    const int lane = threadIdx.x & 31;
    const int ry   = threadIdx.x >> 5;               // 0..7
    const int c    = blockIdx.x * 32 + lane;         // channel
    const int rend = min(M, (int)(blockIdx.y + 1) * 128);
    float s = 0.0f, ss = 0.0f;
    for (int r = blockIdx.y * 128 + ry; r < rend; r += 8) {
        const float v = X[(long)r * 512 + c];
        s += v; ss += v * v;
    }
    __shared__ float shs[8][32], shq[8][32];
    shs[ry][lane] = s; shq[ry][lane] = ss;
    __syncthreads();
    if (ry == 0) {
        #pragma unroll
        for (int i = 1; i < 8; i++) { s += shs[i][lane]; ss += shq[i][lane]; }
        atomicAdd(&gsum[c], s);
        atomicAdd(&gssq[c], ss);
    }
}

__global__ void bn_final(const float* __restrict__ gsum, const float* __restrict__ gssq,
                         float* __restrict__ mean, float* __restrict__ istd, int M)
{
    const int c = threadIdx.x;   // 512 threads
    const float m = gsum[c] / (float)M;
    const float v = gssq[c] / (float)M - m * m;
    mean[c] = m;
    istd[c] = rsqrtf(v + EPSV);
}

__global__ void bn_norm(float* __restrict__ X,
                        const float* __restrict__ gamma, const float* __restrict__ beta,
                        const float* __restrict__ mean, const float* __restrict__ istd,
                        int total)
{
    for (int i = blockIdx.x * blockDim.x + threadIdx.x; i < total;
         i += gridDim.x * blockDim.x) {
        const int c = i & 511;
        const float v = (X[i] - mean[c]) * istd[c] * gamma[c] + beta[c];
        X[i] = v > 0.0f ? v : 0.0f;
    }
}

// ---------------------------------------------------------------------------
// Vector quantization
// ---------------------------------------------------------------------------
__global__ void zero_vq(int* counts, float* loss)
{
    const int i = blockIdx.x * blockDim.x + threadIdx.x;
    if (i < 512) counts[i] = 0;
    if (i == 0)  loss[0] = 0.0f;
}

// dist_k = ||z||^2 + ||c_k||^2 - 2 z.c_k ; argmin over k == argmin(cnorm - 2*score)
__global__ void vq_argmin(const float* __restrict__ scores, const float* __restrict__ cnorm,
                          const float* __restrict__ cb, float* __restrict__ q,
                          int* __restrict__ counts)
{
    const int n = blockIdx.x;       // 1024 blocks
    const int k = threadIdx.x;      // 512 threads
    const float d = cnorm[k] - 2.0f * scores[(long)n * 512 + k];
    __shared__ float sv[512];
    __shared__ int   si[512];
    sv[k] = d; si[k] = k;
    __syncthreads();
    for (int st = 256; st > 0; st >>= 1) {
        if (k < st) {
            const float ov = sv[k + st];
            const int   oi = si[k + st];
            if (ov < sv[k] || (ov == sv[k] && oi < si[k])) { sv[k] = ov; si[k] = oi; }
        }
        __syncthreads();
    }
    const int best = si[0];
    if (k == 0) atomicAdd(&counts[best], 1);
    q[(long)n * 512 + k] = cb[(long)best * 512 + k];
}

__global__ void vq_loss_k(const float* __restrict__ q, const float* __restrict__ z,
                          float* __restrict__ loss)
{
    float s = 0.0f;
    const int total = 1024 * 512;
    for (int i = blockIdx.x * blockDim.x + threadIdx.x; i < total;
         i += gridDim.x * blockDim.x) {
        const float d = q[i] - z[i];
        s += d * d;
    }
    // warp reduce
    #pragma unroll
    for (int o = 16; o > 0; o >>= 1) s += __shfl_down_sync(0xffffffffu, s, o);
    __shared__ float sh[8];
    if ((threadIdx.x & 31) == 0) sh[threadIdx.x >> 5] = s;
    __syncthreads();
    if (threadIdx.x < 8) {
        float t = sh[threadIdx.x];
        #pragma unroll
        for (int o = 4; o > 0; o >>= 1) t += __shfl_down_sync(0xffu, t, o);
        if (threadIdx.x == 0) atomicAdd(loss, t);
    }
}

__global__ void finalize_k(const int* __restrict__ counts, const float* __restrict__ loss,
                           float* __restrict__ out, long outsize)
{
    const int k = threadIdx.x;  // 512
    const float p = (float)counts[k] * (1.0f / 1024.0f);
    __shared__ float sh[512];
    sh[k] = p * logf(p + 1e-10f);
    __syncthreads();
    for (int st = 256; st > 0; st >>= 1) {
        if (k < st) sh[k] += sh[k + st];
        __syncthreads();
    }
    if (k == 0) {
        const long R = 1024L * 30 * 135;
        if (outsize >= R + 2) {
            out[R]     = loss[0] * 1.25f / (1024.0f * 512.0f);   // vq_loss
            out[R + 1] = expf(-sh[0]);                           // perplexity
        }
    }
}

// ---------------------------------------------------------------------------
// Host launch
// ---------------------------------------------------------------------------
static inline dim3 ggrid(int M, int N) { return dim3((N + 63) / 64, (M + 63) / 64); }

static void run_bn(float* X, const float* g, const float* b, int M,
                   float* sum, float* ssq, float* mean, float* istd)
{
    zero_stats<<<2, 256>>>(sum, ssq);
    dim3 gs(16, (M + 127) / 128);
    bn_stats<<<gs, 256>>>(X, M, sum, ssq);
    bn_final<<<1, 512>>>(sum, ssq, mean, istd, M);
    bn_norm<<<2048, 256>>>(X, g, b, mean, istd, M * 512);
}

extern "C" void kernel_launch(void* const* d_in, const int* in_sizes, int n_in,
                              void* d_out, int out_size)
{
    (void)in_sizes; (void)n_in;
    float* buf = nullptr;
    cudaGetSymbolAddress((void**)&buf, g_buf);

    const float* input = (const float*)d_in[0];
    const float* W_in  = (const float*)d_in[1];
    const float* b_in  = (const float*)d_in[2];
    const float* w_e1  = (const float*)d_in[3];
    const float* g_e1  = (const float*)d_in[4];
    const float* b_e1  = (const float*)d_in[5];
    const float* w_e2  = (const float*)d_in[6];
    const float* g_e2  = (const float*)d_in[7];
    const float* b_e2  = (const float*)d_in[8];
    const float* w_e3  = (const float*)d_in[9];
    const float* g_e3  = (const float*)d_in[10];
    const float* b_e3  = (const float*)d_in[11];
    const float* cb    = (const float*)d_in[12];
    const float* W_q   = (const float*)d_in[13];
    const float* b_q   = (const float*)d_in[14];
    const float* w_d1  = (const float*)d_in[15];
    const float* g_d1  = (const float*)d_in[16];
    const float* b_d1  = (const float*)d_in[17];
    const float* w_d2  = (const float*)d_in[18];
    const float* g_d2  = (const float*)d_in[19];
    const float* b_d2  = (const float*)d_in[20];
    const float* w_d3  = (const float*)d_in[21];
    const float* g_d3  = (const float*)d_in[22];
    const float* b_d3  = (const float*)d_in[23];
    const float* W_out = (const float*)d_in[24];
    const float* b_out = (const float*)d_in[25];

    float* x0   = buf + O_X0;
    float* e1   = buf + O_E1;
    float* e2   = buf + O_E2;
    float* z    = buf + O_Z;
    float* q    = buf + O_Q;
    float* d0   = buf + O_D0;
    float* d1   = buf + O_D1;
    float* d2   = buf + O_D2;
    float* d3   = buf + O_D3;
    float* we1t = buf + O_WE1;
    float* we2t = buf + O_WE2;
    float* we3t = buf + O_WE3;
    float* wd1t = buf + O_WD1;
    float* wd2t = buf + O_WD2;
    float* wd3t = buf + O_WD3;
    float* cbT  = buf + O_CBT;
    float* sc   = buf + O_SC;
    float* cn   = buf + O_CN;
    float* sum  = buf + O_SUM;
    float* ssq  = buf + O_SSQ;
    float* mean = buf + O_MEAN;
    float* istd = buf + O_ISTD;
    float* loss = buf + O_LOSS;
    int*   cnt  = (int*)(buf + O_CNT);

    float* out = (float*)d_out;

    // ---- weight prep (cheap) ----
    wt_enc<<<512, 256>>>(w_e1, we1t, 512, 512, 5);
    wt_enc<<<384, 256>>>(w_e2, we2t, 512, 512, 3);
    wt_enc<<<256, 256>>>(w_e3, we3t, 512, 512, 2);
    wt_dec<<<256, 256>>>(w_d1, wd1t, 512, 512, 2);
    wt_dec<<<384, 256>>>(w_d2, wd2t, 512, 512, 3);
    wt_dec<<<512, 256>>>(w_d3, wd3t, 512, 512, 5);
    cb_prep<<<512, 128>>>(cb, cbT, cn);
    zero_vq<<<2, 256>>>(cnt, loss);

    // ---- input GEMM: (t,b) rows x [135 -> 512], permuted to [b, t, c] ----
    gemm_kernel<<<ggrid(30720, 512), 256>>>(input, W_in, b_in, x0,
                                            30720, 512, 135, 1);

    // ---- encoder ----
    gemm_kernel<<<ggrid(6144, 512), 256>>>(x0, we1t, nullptr, e1, 6144, 512, 2560, 0);
    run_bn(e1, g_e1, b_e1, 6144, sum, ssq, mean, istd);

    gemm_kernel<<<ggrid(2048, 512), 256>>>(e1, we2t, nullptr, e2, 2048, 512, 1536, 0);
    run_bn(e2, g_e2, b_e2, 2048, sum, ssq, mean, istd);

    gemm_kernel<<<ggrid(1024, 512), 256>>>(e2, we3t, nullptr, z, 1024, 512, 1024, 0);
    run_bn(z, g_e3, b_e3, 1024, sum, ssq, mean, istd);

    // ---- vector quantization ----
    gemm_kernel<<<ggrid(1024, 512), 256>>>(z, cbT, nullptr, sc, 1024, 512, 512, 0);
    vq_argmin<<<1024, 512>>>(sc, cn, cb, q, cnt);
    vq_loss_k<<<256, 256>>>(q, z, loss);

    // ---- decoder ----
    gemm_kernel<<<ggrid(1024, 512), 256>>>(q, W_q, b_q, d0, 1024, 512, 512, 0);

    gemm_kernel<<<ggrid(1024, 1024), 256>>>(d0, wd1t, nullptr, d1, 1024, 1024, 512, 0);
    run_bn(d1, g_d1, b_d1, 2048, sum, ssq, mean, istd);

    gemm_kernel<<<ggrid(2048, 1536), 256>>>(d1, wd2t, nullptr, d2, 2048, 1536, 512, 0);
    run_bn(d2, g_d2, b_d2, 6144, sum, ssq, mean, istd);

    gemm_kernel<<<ggrid(6144, 2560), 256>>>(d2, wd3t, nullptr, d3, 6144, 2560, 512, 0);
    run_bn(d3, g_d3, b_d3, 30720, sum, ssq, mean, istd);

    // ---- output GEMM -> recon ----
    gemm_kernel<<<ggrid(30720, 135), 256>>>(d3, W_out, b_out, out,
                                            30720, 135, 512, 0);

    // ---- scalars ----
    finalize_k<<<1, 512>>>(cnt, loss, out, (long)out_size);
}

// round 3
// speedup vs baseline: 1.0279x; 1.0279x over previous
#include <cuda_runtime.h>
#include <math.h>
#include <stdint.h>

// ---------------------------------------------------------------------------
// VQ-VAE forward. T=30, B=1024, D_POSE=135, H=512, K_CODES=512.
// Activations stored [b, position, channel] so every conv/convT/linear is a
// plain row-major GEMM. GEMMs run on tensor cores: 3xTF32 (hi/lo split) via
// mma.sync.m16n8k8 for fp32-equivalent accuracy (needed so VQ argmin never
// flips vs the fp32 reference).
// ---------------------------------------------------------------------------

#define EPSV 1e-5f

// ---- scratch buffer (single __device__ global, partitioned by offsets) ----
constexpr long O_X0  = 0;                              // 30720 x 512 (b,t,c)
constexpr long O_E1  = O_X0  + 30720L * 512;           //  6144 x 512
constexpr long O_E2  = O_E1  +  6144L * 512;           //  2048 x 512
constexpr long O_Z   = O_E2  +  2048L * 512;           //  1024 x 512
constexpr long O_Q   = O_Z   +  1024L * 512;           //  1024 x 512 (quantized)
constexpr long O_D0  = O_Q   +  1024L * 512;           //  1024 x 512
constexpr long O_D1  = O_D0  +  1024L * 512;           //  1024 x 1024
constexpr long O_D2  = O_D1  +  2048L * 512;           //  2048 x 1536
constexpr long O_D3  = O_D2  +  6144L * 512;           //  6144 x 2560
constexpr long O_WE1 = O_D3  + 30720L * 512;           //  2560 x 512
constexpr long O_WE2 = O_WE1 +  2560L * 512;           //  1536 x 512
constexpr long O_WE3 = O_WE2 +  1536L * 512;           //  1024 x 512
constexpr long O_WD1 = O_WE3 +  1024L * 512;           //   512 x 1024
constexpr long O_WD2 = O_WD1 +   512L * 1024;          //   512 x 1536
constexpr long O_WD3 = O_WD2 +   512L * 1536;          //   512 x 2560
constexpr long O_CBT = O_WD3 +   512L * 2560;          //   512 x 512 (codebook^T)
constexpr long O_SC  = O_CBT +   512L * 512;           //  1024 x 512 (z . c_k)
constexpr long O_CN  = O_SC  +  1024L * 512;           //   512 codebook norms
constexpr long O_SUM = O_CN  + 512;
constexpr long O_SSQ = O_SUM + 512;
constexpr long O_MEAN= O_SSQ + 512;
constexpr long O_ISTD= O_MEAN + 512;
constexpr long O_LOSS= O_ISTD + 512;                   // [0] used
constexpr long O_CNT = O_LOSS + 512;                   // 512 ints (reinterpret)
constexpr long TOTALF= O_CNT + 512;

__device__ float g_buf[TOTALF];

// ---------------------------------------------------------------------------
// 3xTF32 helpers
// ---------------------------------------------------------------------------
__device__ __forceinline__ void tf32_split(float x, float& h, float& l)
{
    uint32_t hb;
    asm("cvt.rna.tf32.f32 %0, %1;" : "=r"(hb) : "f"(x));
    h = __uint_as_float(hb);
    float r = x - h;                  // exact in fp32
    uint32_t lb;
    asm("cvt.rna.tf32.f32 %0, %1;" : "=r"(lb) : "f"(r));
    l = __uint_as_float(lb);
}

__device__ __forceinline__ void mma_tf32(float* c, const uint32_t* a, const uint32_t* b)
{
    asm volatile(
        "mma.sync.aligned.m16n8k8.row.col.f32.tf32.tf32.f32 "
        "{%0,%1,%2,%3}, {%4,%5,%6,%7}, {%8,%9}, {%0,%1,%2,%3};"
        : "+f"(c[0]), "+f"(c[1]), "+f"(c[2]), "+f"(c[3])
        : "r"(a[0]), "r"(a[1]), "r"(a[2]), "r"(a[3]), "r"(b[0]), "r"(b[1]));
}

// ---------------------------------------------------------------------------
// GEMM: C[M,N] = A[M,K] * B[K,N] (+bias), 3xTF32 tensor cores.
// Block tile 128x64, BK=16, 256 threads (8 warps: 4 along M, 2 along N).
// Warp tile 32x32 = 2 m16-tiles x 4 n8-tiles.
// SMEM rows padded to 20 words -> conflict-free fragment LDS.
// Vector (float4) global loads are used ONLY when the row stride is a
// multiple of 4 floats (K%4 for A, N%4 for B) — the 135-dim GEMMs fall back
// to scalar loads (misaligned-address fix).
// perm==1: output row remap r=(t*1024+b) -> b*30+t (input GEMM only).
// ---------------------------------------------------------------------------
__global__ __launch_bounds__(256, 2)
void gemm_tc(const float* __restrict__ A, const float* __restrict__ B,
             const float* __restrict__ bias, float* __restrict__ C,
             int M, int N, int K, int perm)
{
    __shared__ float Ah[128][20], Al[128][20];
    __shared__ float Bh[64][20],  Bl[64][20];

    const int tid  = threadIdx.x;
    const int lane = tid & 31;
    const int w    = tid >> 5;
    const int wm   = (w & 3) * 32;   // warp M offset in tile
    const int wn   = (w >> 2) * 32;  // warp N offset in tile
    const int g    = lane >> 2;      // group id 0..7
    const int t    = lane & 3;       // thread-in-group 0..3
    const int m0   = blockIdx.y * 128;
    const int n0   = blockIdx.x * 64;

    const bool avec = ((K & 3) == 0);
    const bool bvec = ((N & 3) == 0);

    float acc[2][4][4];
    #pragma unroll
    for (int i = 0; i < 2; i++)
        #pragma unroll
        for (int j = 0; j < 4; j++)
            #pragma unroll
            for (int k = 0; k < 4; k++) acc[i][j][k] = 0.0f;

    for (int k0 = 0; k0 < K; k0 += 16) {
        // ---- load A tile 128x16 (2 quads per thread), split hi/lo ----
        #pragma unroll
        for (int i = 0; i < 2; i++) {
            const int idx = tid + i * 256;       // 0..511 quad slots
            const int row = idx >> 2;
            const int kq  = (idx & 3) << 2;
            const int gm  = m0 + row;
            const int gk  = k0 + kq;
            float v[4] = {0.f, 0.f, 0.f, 0.f};
            if (gm < M) {
                if (avec && gk + 3 < K) {
                    const float4 f = *(const float4*)&A[(long)gm * K + gk];
                    v[0] = f.x; v[1] = f.y; v[2] = f.z; v[3] = f.w;
                } else {
                    #pragma unroll
                    for (int j = 0; j < 4; j++)
                        if (gk + j < K) v[j] = A[(long)gm * K + gk + j];
                }
            }
            #pragma unroll
            for (int j = 0; j < 4; j++) {
                float h, l;
                tf32_split(v[j], h, l);
                Ah[row][kq + j] = h;
                Al[row][kq + j] = l;
            }
        }
        // ---- load B tile 16x64 (1 quad per thread), split, store [n][k] ----
        {
            const int kr = tid >> 4;             // 0..15
            const int nq = (tid & 15) << 2;      // 0..60
            const int gk = k0 + kr;
            float v[4] = {0.f, 0.f, 0.f, 0.f};
            if (gk < K) {
                if (bvec && n0 + nq + 3 < N) {
                    const float4 f = *(const float4*)&B[(long)gk * N + n0 + nq];
                    v[0] = f.x; v[1] = f.y; v[2] = f.z; v[3] = f.w;
                } else {
                    #pragma unroll
                    for (int j = 0; j < 4; j++)
                        if (n0 + nq + j < N) v[j] = B[(long)gk * N + n0 + nq + j];
                }
            }
            #pragma unroll
            for (int j = 0; j < 4; j++) {
                float h, l;
                tf32_split(v[j], h, l);
                Bh[nq + j][kr] = h;
                Bl[nq + j][kr] = l;
            }
        }
        __syncthreads();

        // ---- compute: two k8 steps ----
        #pragma unroll
        for (int ks = 0; ks < 16; ks += 8) {
            uint32_t ah[2][4], al[2][4], bh[4][2], bl[4][2];
            #pragma unroll
            for (int mt = 0; mt < 2; mt++) {
                const int mb = wm + mt * 16;
                ah[mt][0] = __float_as_uint(Ah[mb + g    ][ks + t    ]);
                ah[mt][1] = __float_as_uint(Ah[mb + g + 8][ks + t    ]);
                ah[mt][2] = __float_as_uint(Ah[mb + g    ][ks + t + 4]);
                ah[mt][3] = __float_as_uint(Ah[mb + g + 8][ks + t + 4]);
                al[mt][0] = __float_as_uint(Al[mb + g    ][ks + t    ]);
                al[mt][1] = __float_as_uint(Al[mb + g + 8][ks + t    ]);
                al[mt][2] = __float_as_uint(Al[mb + g    ][ks + t + 4]);
                al[mt][3] = __float_as_uint(Al[mb + g + 8][ks + t + 4]);
            }
            #pragma unroll
            for (int nt = 0; nt < 4; nt++) {
                const int nb = wn + nt * 8;
                bh[nt][0] = __float_as_uint(Bh[nb + g][ks + t    ]);
                bh[nt][1] = __float_as_uint(Bh[nb + g][ks + t + 4]);
                bl[nt][0] = __float_as_uint(Bl[nb + g][ks + t    ]);
                bl[nt][1] = __float_as_uint(Bl[nb + g][ks + t + 4]);
            }
            #pragma unroll
            for (int mt = 0; mt < 2; mt++)
                #pragma unroll
                for (int nt = 0; nt < 4; nt++) {
                    mma_tf32(acc[mt][nt], ah[mt], bl[nt]);   // hi*lo
                    mma_tf32(acc[mt][nt], al[mt], bh[nt]);   // lo*hi
                    mma_tf32(acc[mt][nt], ah[mt], bh[nt]);   // hi*hi
                }
        }
        __syncthreads();
    }

    // ---- epilogue ----
    #pragma unroll
    for (int mt = 0; mt < 2; mt++) {
        #pragma unroll
        for (int nt = 0; nt < 4; nt++) {
            const int cbase = n0 + wn + nt * 8 + t * 2;
            #pragma unroll
            for (int half = 0; half < 2; half++) {
                const int gm = m0 + wm + mt * 16 + g + half * 8;
                if (gm >= M) continue;
                const int orow = perm ? ((gm & 1023) * 30 + (gm >> 10)) : gm;
                #pragma unroll
                for (int j = 0; j < 2; j++) {
                    const int gn = cbase + j;
                    if (gn >= N) continue;
                    float v = acc[mt][nt][half * 2 + j];
                    if (bias) v += bias[gn];
                    C[(long)orow * N + gn] = v;
                }
            }
        }
    }
}

// ---------------------------------------------------------------------------
// Weight re-layout kernels.
// encoder: wt[(k*I+i)*O + o] = w[o, i, k]   (w shape O,I,Kk)
// decoder: wt[i*(Kk*O) + k*O + o] = w[i, o, k]  (w shape I,O,Kk)
// ---------------------------------------------------------------------------
__global__ void wt_enc(const float* __restrict__ w, float* __restrict__ wt,
                       int I, int O, int Kk)
{
    const int n = I * O * Kk;
    for (int j = blockIdx.x * blockDim.x + threadIdx.x; j < n;
         j += gridDim.x * blockDim.x) {
        const int o = j % O;
        const int rest = j / O;       // k*I + i
        const int i = rest % I;
        const int k = rest / I;
        wt[j] = w[(long)o * I * Kk + (long)i * Kk + k];
    }
}

__global__ void wt_dec(const float* __restrict__ w, float* __restrict__ wt,
                       int I, int O, int Kk)
{
    const int n = I * O * Kk;
    for (int j = blockIdx.x * blockDim.x + threadIdx.x; j < n;
         j += gridDim.x * blockDim.x) {
        const int o = j % O;
        const int rest = j / O;       // i*Kk + k
        const int k = rest % Kk;
        const int i = rest / Kk;
        wt[j] = w[(long)i * O * Kk + (long)o * Kk + k];
    }
}

// codebook transpose + per-code squared norm
__global__ void cb_prep(const float* __restrict__ cb, float* __restrict__ cbT,
                        float* __restrict__ cnorm)
{
    const int k = blockIdx.x;
    float s = 0.0f;
    for (int d = threadIdx.x; d < 512; d += 128) {
        const float v = cb[k * 512 + d];
        s += v * v;
        cbT[d * 512 + k] = v;
    }
    __shared__ float sh[128];
    sh[threadIdx.x] = s;
    __syncthreads();
    for (int st = 64; st > 0; st >>= 1) {
        if (threadIdx.x < st) sh[threadIdx.x] += sh[threadIdx.x + st];
        __syncthreads();
    }
    if (threadIdx.x == 0) cnorm[k] = sh[0];
}

// ---------------------------------------------------------------------------
// BatchNorm(+ReLU)
// ---------------------------------------------------------------------------
__global__ void zero_stats(float* a, float* b)
{
    const int i = blockIdx.x * blockDim.x + threadIdx.x;
    if (i < 512) { a[i] = 0.0f; b[i] = 0.0f; }
}

__global__ void bn_stats(const float* __restrict__ X, int M,
                         float* __restrict__ gsum, float* __restrict__ gssq)
{
    const int lane = threadIdx.x & 31;
    const int ry   = threadIdx.x >> 5;
    const int c    = blockIdx.x * 32 + lane;
    const int rend = min(M, (int)(blockIdx.y + 1) * 128);
    float s = 0.0f, ss = 0.0f;
    for (int r = blockIdx.y * 128 + ry; r < rend; r += 8) {
        const float v = X[(long)r * 512 + c];
        s += v; ss += v * v;
    }
    __shared__ float shs[8][32], shq[8][32];
    shs[ry][lane] = s; shq[ry][lane] = ss;
    __syncthreads();
    if (ry == 0) {
        #pragma unroll
        for (int i = 1; i < 8; i++) { s += shs[i][lane]; ss += shq[i][lane]; }
        atomicAdd(&gsum[c], s);
        atomicAdd(&gssq[c], ss);
    }
}

__global__ void bn_final(const float* __restrict__ gsum, const float* __restrict__ gssq,
                         float* __restrict__ mean, float* __restrict__ istd, int M)
{
    const int c = threadIdx.x;
    const float m = gsum[c] / (float)M;
    const float v = gssq[c] / (float)M - m * m;
    mean[c] = m;
    istd[c] = rsqrtf(v + EPSV);
}

__global__ void bn_norm(float* __restrict__ X,
                        const float* __restrict__ gamma, const float* __restrict__ beta,
                        const float* __restrict__ mean, const float* __restrict__ istd,
                        int total)
{
    for (int i = blockIdx.x * blockDim.x + threadIdx.x; i < total;
         i += gridDim.x * blockDim.x) {
        const int c = i & 511;
        const float v = (X[i] - mean[c]) * istd[c] * gamma[c] + beta[c];
        X[i] = v > 0.0f ? v : 0.0f;
    }
}

// ---------------------------------------------------------------------------
// Vector quantization
// ---------------------------------------------------------------------------
__global__ void zero_vq(int* counts, float* loss)
{
    const int i = blockIdx.x * blockDim.x + threadIdx.x;
    if (i < 512) counts[i] = 0;
    if (i == 0)  loss[0] = 0.0f;
}

__global__ void vq_argmin(const float* __restrict__ scores, const float* __restrict__ cnorm,
                          const float* __restrict__ cb, float* __restrict__ q,
                          int* __restrict__ counts)
{
    const int n = blockIdx.x;
    const int k = threadIdx.x;
    const float d = cnorm[k] - 2.0f * scores[(long)n * 512 + k];
    __shared__ float sv[512];
    __shared__ int   si[512];
    sv[k] = d; si[k] = k;
    __syncthreads();
    for (int st = 256; st > 0; st >>= 1) {
        if (k < st) {
            const float ov = sv[k + st];
            const int   oi = si[k + st];
            if (ov < sv[k] || (ov == sv[k] && oi < si[k])) { sv[k] = ov; si[k] = oi; }
        }
        __syncthreads();
    }
    const int best = si[0];
    if (k == 0) atomicAdd(&counts[best], 1);
    q[(long)n * 512 + k] = cb[(long)best * 512 + k];
}

__global__ void vq_loss_k(const float* __restrict__ q, const float* __restrict__ z,
                          float* __restrict__ loss)
{
    float s = 0.0f;
    const int total = 1024 * 512;
    for (int i = blockIdx.x * blockDim.x + threadIdx.x; i < total;
         i += gridDim.x * blockDim.x) {
        const float d = q[i] - z[i];
        s += d * d;
    }
    #pragma unroll
    for (int o = 16; o > 0; o >>= 1) s += __shfl_down_sync(0xffffffffu, s, o);
    __shared__ float sh[8];
    if ((threadIdx.x & 31) == 0) sh[threadIdx.x >> 5] = s;
    __syncthreads();
    if (threadIdx.x < 8) {
        float t = sh[threadIdx.x];
        #pragma unroll
        for (int o = 4; o > 0; o >>= 1) t += __shfl_down_sync(0xffu, t, o);
        if (threadIdx.x == 0) atomicAdd(loss, t);
    }
}

__global__ void finalize_k(const int* __restrict__ counts, const float* __restrict__ loss,
                           float* __restrict__ out, long outsize)
{
    const int k = threadIdx.x;
    const float p = (float)counts[k] * (1.0f / 1024.0f);
    __shared__ float sh[512];
    sh[k] = p * logf(p + 1e-10f);
    __syncthreads();
    for (int st = 256; st > 0; st >>= 1) {
        if (k < st) sh[k] += sh[k + st];
        __syncthreads();
    }
    if (k == 0) {
        const long R = 1024L * 30 * 135;
        if (outsize >= R + 2) {
            out[R]     = loss[0] * 1.25f / (1024.0f * 512.0f);
            out[R + 1] = expf(-sh[0]);
        }
    }
}

// ---------------------------------------------------------------------------
// Host launch
// ---------------------------------------------------------------------------
static inline dim3 ggrid(int M, int N) { return dim3((N + 63) / 64, (M + 127) / 128); }

static void run_bn(float* X, const float* g, const float* b, int M,
                   float* sum, float* ssq, float* mean, float* istd)
{
    zero_stats<<<2, 256>>>(sum, ssq);
    dim3 gs(16, (M + 127) / 128);
    bn_stats<<<gs, 256>>>(X, M, sum, ssq);
    bn_final<<<1, 512>>>(sum, ssq, mean, istd, M);
    bn_norm<<<2048, 256>>>(X, g, b, mean, istd, M * 512);
}

extern "C" void kernel_launch(void* const* d_in, const int* in_sizes, int n_in,
                              void* d_out, int out_size)
{
    (void)in_sizes; (void)n_in;
    float* buf = nullptr;
    cudaGetSymbolAddress((void**)&buf, g_buf);

    const float* input = (const float*)d_in[0];
    const float* W_in  = (const float*)d_in[1];
    const float* b_in  = (const float*)d_in[2];
    const float* w_e1  = (const float*)d_in[3];
    const float* g_e1  = (const float*)d_in[4];
    const float* b_e1  = (const float*)d_in[5];
    const float* w_e2  = (const float*)d_in[6];
    const float* g_e2  = (const float*)d_in[7];
    const float* b_e2  = (const float*)d_in[8];
    const float* w_e3  = (const float*)d_in[9];
    const float* g_e3  = (const float*)d_in[10];
    const float* b_e3  = (const float*)d_in[11];
    const float* cb    = (const float*)d_in[12];
    const float* W_q   = (const float*)d_in[13];
    const float* b_q   = (const float*)d_in[14];
    const float* w_d1  = (const float*)d_in[15];
    const float* g_d1  = (const float*)d_in[16];
    const float* b_d1  = (const float*)d_in[17];
    const float* w_d2  = (const float*)d_in[18];
    const float* g_d2  = (const float*)d_in[19];
    const float* b_d2  = (const float*)d_in[20];
    const float* w_d3  = (const float*)d_in[21];
    const float* g_d3  = (const float*)d_in[22];
    const float* b_d3  = (const float*)d_in[23];
    const float* W_out = (const float*)d_in[24];
    const float* b_out = (const float*)d_in[25];

    float* x0   = buf + O_X0;
    float* e1   = buf + O_E1;
    float* e2   = buf + O_E2;
    float* z    = buf + O_Z;
    float* q    = buf + O_Q;
    float* d0   = buf + O_D0;
    float* d1   = buf + O_D1;
    float* d2   = buf + O_D2;
    float* d3   = buf + O_D3;
    float* we1t = buf + O_WE1;
    float* we2t = buf + O_WE2;
    float* we3t = buf + O_WE3;
    float* wd1t = buf + O_WD1;
    float* wd2t = buf + O_WD2;
    float* wd3t = buf + O_WD3;
    float* cbT  = buf + O_CBT;
    float* sc   = buf + O_SC;
    float* cn   = buf + O_CN;
    float* sum  = buf + O_SUM;
    float* ssq  = buf + O_SSQ;
    float* mean = buf + O_MEAN;
    float* istd = buf + O_ISTD;
    float* loss = buf + O_LOSS;
    int*   cnt  = (int*)(buf + O_CNT);

    float* out = (float*)d_out;

    // ---- weight prep ----
    wt_enc<<<512, 256>>>(w_e1, we1t, 512, 512, 5);
    wt_enc<<<384, 256>>>(w_e2, we2t, 512, 512, 3);
    wt_enc<<<256, 256>>>(w_e3, we3t, 512, 512, 2);
    wt_dec<<<256, 256>>>(w_d1, wd1t, 512, 512, 2);
    wt_dec<<<384, 256>>>(w_d2, wd2t, 512, 512, 3);
    wt_dec<<<512, 256>>>(w_d3, wd3t, 512, 512, 5);
    cb_prep<<<512, 128>>>(cb, cbT, cn);
    zero_vq<<<2, 256>>>(cnt, loss);

    // ---- input GEMM: (t,b) rows x [135 -> 512], permuted to [b, t, c] ----
    gemm_tc<<<ggrid(30720, 512), 256>>>(input, W_in, b_in, x0, 30720, 512, 135, 1);

    // ---- encoder ----
    gemm_tc<<<ggrid(6144, 512), 256>>>(x0, we1t, nullptr, e1, 6144, 512, 2560, 0);
    run_bn(e1, g_e1, b_e1, 6144, sum, ssq, mean, istd);

    gemm_tc<<<ggrid(2048, 512), 256>>>(e1, we2t, nullptr, e2, 2048, 512, 1536, 0);
    run_bn(e2, g_e2, b_e2, 2048, sum, ssq, mean, istd);

    gemm_tc<<<ggrid(1024, 512), 256>>>(e2, we3t, nullptr, z, 1024, 512, 1024, 0);
    run_bn(z, g_e3, b_e3, 1024, sum, ssq, mean, istd);

    // ---- vector quantization ----
    gemm_tc<<<ggrid(1024, 512), 256>>>(z, cbT, nullptr, sc, 1024, 512, 512, 0);
    vq_argmin<<<1024, 512>>>(sc, cn, cb, q, cnt);
    vq_loss_k<<<256, 256>>>(q, z, loss);

    // ---- decoder ----
    gemm_tc<<<ggrid(1024, 512), 256>>>(q, W_q, b_q, d0, 1024, 512, 512, 0);

    gemm_tc<<<ggrid(1024, 1024), 256>>>(d0, wd1t, nullptr, d1, 1024, 1024, 512, 0);
    run_bn(d1, g_d1, b_d1, 2048, sum, ssq, mean, istd);

    gemm_tc<<<ggrid(2048, 1536), 256>>>(d1, wd2t, nullptr, d2, 2048, 1536, 512, 0);
    run_bn(d2, g_d2, b_d2, 6144, sum, ssq, mean, istd);

    gemm_tc<<<ggrid(6144, 2560), 256>>>(d2, wd3t, nullptr, d3, 6144, 2560, 512, 0);
    run_bn(d3, g_d3, b_d3, 30720, sum, ssq, mean, istd);

    // ---- output GEMM -> recon ----
    gemm_tc<<<ggrid(30720, 135), 256>>>(d3, W_out, b_out, out, 30720, 135, 512, 0);

    // ---- scalars ----
    finalize_k<<<1, 512>>>(cnt, loss, out, (long)out_size);
}

// round 6
// speedup vs baseline: 2.2000x; 2.1403x over previous
#include <cuda_runtime.h>
#include <cuda_fp16.h>
#include <math.h>
#include <stdint.h>

// ---------------------------------------------------------------------------
// VQ-VAE forward. T=30, B=1024, D_POSE=135, H=512, K_CODES=512.
// Activations stored [b, position, channel] -> every conv/convT/linear is a
// plain row-major GEMM: C[M,N] = A[M,K] * B'[N,K]^T.
// GEMMs: mma.sync.m16n8k16 f16 with 3xFP16 hi/lo split (error ~2^-24) so the
// VQ argmin never flips vs fp32. Weights pre-split to f16 pairs in prep.
// (tcgen05 is unavailable: harness compiles via compute_103 virtual arch.)
// ---------------------------------------------------------------------------

#define EPSV 1e-5f

// ======================= fp32 scratch ======================================
constexpr long O_X0  = 0;                               // 30720 x 512
constexpr long O_E1  = O_X0  + 30720L * 512;            //  6144 x 512
constexpr long O_E2  = O_E1  +  6144L * 512;            //  2048 x 512
constexpr long O_Z   = O_E2  +  2048L * 512;            //  1024 x 512
constexpr long O_Q   = O_Z   +  1024L * 512;            //  1024 x 512
constexpr long O_D0  = O_Q   +  1024L * 512;            //  1024 x 512
constexpr long O_D1  = O_D0  +  1024L * 512;            //  1024 x 1024
constexpr long O_D2  = O_D1  +  2048L * 512;            //  2048 x 1536
constexpr long O_D3  = O_D2  +  6144L * 512;            //  6144 x 2560
constexpr long O_SC  = O_D3  + 30720L * 512;            //  1024 x 512
constexpr long O_CN  = O_SC  +  1024L * 512;            //  512
constexpr long O_STAT= O_CN  + 512;                     //  6 x 2 x 512
constexpr long O_LOSS= O_STAT+ 6L * 2 * 512;
constexpr long O_CNT = O_LOSS+ 512;
constexpr long TOTALF= O_CNT + 512;

__device__ float g_buf[TOTALF];

// ======================= f16 split-weight scratch ==========================
// Each weight stored as [N, Kp] twice (hi then lo), Kp = K rounded to 32.
constexpr long H_WE1 = 0;                               // [512,2560]
constexpr long H_WE2 = H_WE1 + 2L * 512 * 2560;         // [512,1536]
constexpr long H_WE3 = H_WE2 + 2L * 512 * 1536;         // [512,1024]
constexpr long H_WD1 = H_WE3 + 2L * 512 * 1024;         // [1024,512]
constexpr long H_WD2 = H_WD1 + 2L * 1024 * 512;         // [1536,512]
constexpr long H_WD3 = H_WD2 + 2L * 1536 * 512;         // [2560,512]
constexpr long H_WIT = H_WD3 + 2L * 2560 * 512;         // [512,160] (K=135 pad)
constexpr long H_WQT = H_WIT + 2L * 512 * 160;          // [512,512]
constexpr long H_WOT = H_WQT + 2L * 512 * 512;          // [135,512]
constexpr long H_CB  = H_WOT + 2L * 135 * 512;          // [512,512]
constexpr long TOTALH= H_CB  + 2L * 512 * 512;

__device__ __half g_hbuf[TOTALH];

// ======================= helpers ===========================================
__device__ __forceinline__ uint32_t smem_u32(const void* p)
{
    return (uint32_t)__cvta_generic_to_shared(p);
}

__device__ __forceinline__ void f16split(float x, __half& h, __half& l)
{
    h = __float2half_rn(x);
    l = __float2half_rn(x - __half2float(h));
}

__device__ __forceinline__ void mma_f16(float* c, const uint32_t* a, const uint32_t* b)
{
    asm volatile(
        "mma.sync.aligned.m16n8k16.row.col.f32.f16.f16.f32 "
        "{%0,%1,%2,%3}, {%4,%5,%6,%7}, {%8,%9}, {%0,%1,%2,%3};"
        : "+f"(c[0]), "+f"(c[1]), "+f"(c[2]), "+f"(c[3])
        : "r"(a[0]), "r"(a[1]), "r"(a[2]), "r"(a[3]), "r"(b[0]), "r"(b[1]));
}

__device__ __forceinline__ void ldm4(uint32_t& r0, uint32_t& r1, uint32_t& r2,
                                     uint32_t& r3, uint32_t addr)
{
    asm volatile("ldmatrix.sync.aligned.m8n8.x4.shared.b16 {%0,%1,%2,%3}, [%4];"
                 : "=r"(r0), "=r"(r1), "=r"(r2), "=r"(r3) : "r"(addr));
}

__device__ __forceinline__ void cp16(uint32_t dst, const void* src, int pred)
{
    asm volatile("cp.async.cg.shared.global [%0], [%1], 16, %2;"
                 :: "r"(dst), "l"(src), "r"(pred ? 16 : 0) : "memory");
}
__device__ __forceinline__ void cp_commit()
{
    asm volatile("cp.async.commit_group;" ::: "memory");
}

// ======================= GEMM ==============================================
// CTA tile 128x128, BK=32, 256 threads, 8 warps (4 along M x 2 along N),
// warp tile 32x64. SMEM rows = 16 u32 words (32 halves) padded to 20 words
// (row stride 80B = 5 x 16B groups, odd -> conflict-free ldmatrix).
// perm==1: output row remap r=(t*1024+b) -> b*30+t (input GEMM only).

constexpr int ROWW   = 20;                   // words per smem row
constexpr int OFF_A0 = 0;
constexpr int OFF_A1 = 128 * ROWW * 4;       // 10240
constexpr int OFF_B0 = 2 * 128 * ROWW * 4;   // 20480
constexpr int OFF_B1 = 3 * 128 * ROWW * 4;   // 30720
constexpr int STAGE  = 4 * 128 * ROWW * 4;   // 40960
constexpr int DSMEM  = 2 * STAGE + 1024;

__global__ __launch_bounds__(256)
void gemm_h3(const float* __restrict__ A,
             const __half* __restrict__ B0, const __half* __restrict__ B1,
             const float* __restrict__ bias, float* __restrict__ C,
             int M, int N, int K, int Kp, int perm)
{
    extern __shared__ char dsm[];
    const uint32_t dynb = smem_u32(dsm);
    const uint32_t base = (dynb + 1023u) & ~1023u;
    char* smg = dsm + (base - dynb);

    const int tid  = threadIdx.x;
    const int wid  = tid >> 5;
    const int lane = tid & 31;
    const int wm   = (wid & 3) * 32;
    const int wn   = (wid >> 2) * 64;
    const int g    = lane >> 2;
    const int t    = lane & 3;
    const int m0   = blockIdx.y * 128;
    const int n0   = blockIdx.x * 128;

    const bool kvec = ((K & 3) == 0);
    const int  nk   = (K + 31) >> 5;

    // per-thread load coordinates
    const int arow = tid >> 3;              // 0..31 (base row, 4 chunks of 32 rows? no:)
    // A: 1024 float4-quads per tile; idx = tid + i*256; row=idx>>3, kq=(idx&7)*4
    // B: 512 16B-chunks per split; cid = tid + i*256; row=cid>>2, ch=cid&3
    (void)arow;

    float4 vals[4], vnext[4];

    // ---- A tile global load into regs ----
    auto loadA = [&](int k0, float4* v) {
        #pragma unroll
        for (int i = 0; i < 4; ++i) {
            const int idx = tid + i * 256;
            const int row = idx >> 3;
            const int kq  = (idx & 7) << 2;
            const int gm  = m0 + row;
            const int gk  = k0 + kq;
            if (kvec && gk + 3 < K) {
                v[i] = *(const float4*)&A[(long)gm * K + gk];
            } else {
                float x0 = (gk + 0 < K) ? A[(long)gm * K + gk + 0] : 0.f;
                float x1 = (gk + 1 < K) ? A[(long)gm * K + gk + 1] : 0.f;
                float x2 = (gk + 2 < K) ? A[(long)gm * K + gk + 2] : 0.f;
                float x3 = (gk + 3 < K) ? A[(long)gm * K + gk + 3] : 0.f;
                v[i] = make_float4(x0, x1, x2, x3);
            }
        }
    };

    auto stsA = [&](const float4* v, char* stg) {
        #pragma unroll
        for (int i = 0; i < 4; ++i) {
            const int idx = tid + i * 256;
            const int row = idx >> 3;
            const int kq  = (idx & 7) << 2;
            __half h0, l0, h1, l1, h2, l2, h3, l3;
            f16split(v[i].x, h0, l0);
            f16split(v[i].y, h1, l1);
            f16split(v[i].z, h2, l2);
            f16split(v[i].w, h3, l3);
            const int w0 = row * ROWW + (kq >> 1);
            *(__half2*)(stg + OFF_A0 + w0 * 4)     = __halves2half2(h0, h1);
            *(__half2*)(stg + OFF_A0 + w0 * 4 + 4) = __halves2half2(h2, h3);
            *(__half2*)(stg + OFF_A1 + w0 * 4)     = __halves2half2(l0, l1);
            *(__half2*)(stg + OFF_A1 + w0 * 4 + 4) = __halves2half2(l2, l3);
        }
    };

    auto issueB = [&](int k0, uint32_t stg_u) {
        #pragma unroll
        for (int i = 0; i < 2; ++i) {
            const int cid = tid + i * 256;
            const int row = cid >> 2;
            const int ch  = cid & 3;
            const int gn  = n0 + row;
            const int ok  = (gn < N);
            const long so = (long)(ok ? gn : 0) * Kp + k0 + ch * 8;
            cp16(stg_u + OFF_B0 + row * 80 + ch * 16, B0 + so, ok);
            cp16(stg_u + OFF_B1 + row * 80 + ch * 16, B1 + so, ok);
        }
    };

    float acc[2][8][4];
    #pragma unroll
    for (int a = 0; a < 2; a++)
        #pragma unroll
        for (int b = 0; b < 8; b++)
            #pragma unroll
            for (int c = 0; c < 4; c++) acc[a][b][c] = 0.f;

    // ---- prologue ----
    loadA(0, vals);
    issueB(0, base);
    cp_commit();

    for (int it = 0; it < nk; ++it) {
        const int s = it & 1;
        char*    stg   = smg  + s * STAGE;
        const uint32_t stg_u = base + (uint32_t)s * STAGE;

        if (it + 1 < nk) loadA((it + 1) << 5, vnext);
        stsA(vals, stg);
        if (it + 1 < nk) {
            issueB((it + 1) << 5, base + (uint32_t)((s ^ 1)) * STAGE);
            cp_commit();
            asm volatile("cp.async.wait_group 1;" ::: "memory");
        } else {
            asm volatile("cp.async.wait_group 0;" ::: "memory");
        }
        __syncthreads();

        // ---- compute: 2 k16 steps ----
        #pragma unroll
        for (int ks = 0; ks < 2; ++ks) {
            uint32_t aH[2][4], aL[2][4];
            {
                const int arw = (lane & 15);
                const int kwo = ks * 8 + (lane >> 4) * 4;
                #pragma unroll
                for (int mt = 0; mt < 2; ++mt) {
                    const uint32_t ad = stg_u + ((wm + mt * 16 + arw) * ROWW + kwo) * 4;
                    ldm4(aH[mt][0], aH[mt][1], aH[mt][2], aH[mt][3], ad + OFF_A0);
                    ldm4(aL[mt][0], aL[mt][1], aL[mt][2], aL[mt][3], ad + OFF_A1);
                }
            }
            const int brw = (lane >> 4) * 8 + (lane & 7);
            const int bkw = ks * 8 + ((lane >> 3) & 1) * 4;
            #pragma unroll
            for (int p = 0; p < 4; ++p) {
                uint32_t bH[4], bL[4];
                const uint32_t bd = stg_u + ((wn + p * 16 + brw) * ROWW + bkw) * 4;
                ldm4(bH[0], bH[1], bH[2], bH[3], bd + OFF_B0);
                ldm4(bL[0], bL[1], bL[2], bL[3], bd + OFF_B1);
                #pragma unroll
                for (int sub = 0; sub < 2; ++sub) {
                    const int nt = 2 * p + sub;
                    uint32_t b_h[2] = {bH[sub * 2], bH[sub * 2 + 1]};
                    uint32_t b_l[2] = {bL[sub * 2], bL[sub * 2 + 1]};
                    #pragma unroll
                    for (int mt = 0; mt < 2; ++mt) {
                        mma_f16(acc[mt][nt], aH[mt], b_h);
                        mma_f16(acc[mt][nt], aH[mt], b_l);
                        mma_f16(acc[mt][nt], aL[mt], b_h);
                    }
                }
            }
        }
        __syncthreads();

        #pragma unroll
        for (int i = 0; i < 4; ++i) vals[i] = vnext[i];
    }

    // ---- epilogue ----
    const bool neven = ((N & 1) == 0);
    #pragma unroll
    for (int mt = 0; mt < 2; ++mt) {
        #pragma unroll
        for (int half = 0; half < 2; ++half) {
            const int gm = m0 + wm + mt * 16 + g + half * 8;
            if (gm >= M) continue;
            const int orow = perm ? ((gm & 1023) * 30 + (gm >> 10)) : gm;
            #pragma unroll
            for (int nt = 0; nt < 8; ++nt) {
                const int col = n0 + wn + nt * 8 + t * 2;
                const float v0 = acc[mt][nt][half * 2 + 0] + (bias ? (col     < N ? bias[col]     : 0.f) : 0.f);
                const float v1 = acc[mt][nt][half * 2 + 1] + (bias ? (col + 1 < N ? bias[col + 1] : 0.f) : 0.f);
                if (neven && col + 1 < N) {
                    *(float2*)&C[(long)orow * N + col] = make_float2(v0, v1);
                } else {
                    if (col     < N) C[(long)orow * N + col]     = v0;
                    if (col + 1 < N) C[(long)orow * N + col + 1] = v1;
                }
            }
        }
    }
}

// ======================= weight prep (fused transform + f16 split) =========
// encoder: B'[o][k*I+i] = w[o,i,k]; stored [O][Kp] hi/lo
__global__ void wp_enc(const float* __restrict__ w, __half* __restrict__ h0,
                       __half* __restrict__ h1, int I, int O, int Kk, int Kp)
{
    const int Ke = I * Kk;
    const int n  = O * Kp;
    for (int j = blockIdx.x * blockDim.x + threadIdx.x; j < n;
         j += gridDim.x * blockDim.x) {
        const int o  = j / Kp;
        const int kk = j % Kp;
        float x = 0.f;
        if (kk < Ke) {
            const int i = kk % I;
            const int k = kk / I;
            x = w[(long)o * Ke + (long)i * Kk + k];
        }
        __half h, l; f16split(x, h, l);
        h0[j] = h; h1[j] = l;
    }
}

// decoder: B'[(k*O+o)][i] = w[i,o,k]; N = Kk*O, K = I
__global__ void wp_dec(const float* __restrict__ w, __half* __restrict__ h0,
                       __half* __restrict__ h1, int I, int O, int Kk)
{
    const int n = Kk * O * I;
    for (int j = blockIdx.x * blockDim.x + threadIdx.x; j < n;
         j += gridDim.x * blockDim.x) {
        const int i  = j % I;
        const int nn = j / I;
        const int o  = nn % O;
        const int k  = nn / O;
        const float x = w[(long)i * O * Kk + (long)o * Kk + k];
        __half h, l; f16split(x, h, l);
        h0[j] = h; h1[j] = l;
    }
}

// transpose: in [R,C] -> out [C][Kp] (K=R), zero-pad
__global__ void wp_tr(const float* __restrict__ in, __half* __restrict__ h0,
                      __half* __restrict__ h1, int R, int C, int Kp)
{
    const int n = C * Kp;
    for (int j = blockIdx.x * blockDim.x + threadIdx.x; j < n;
         j += gridDim.x * blockDim.x) {
        const int c = j / Kp;
        const int r = j % Kp;
        const float x = (r < R) ? in[(long)r * C + c] : 0.f;
        __half h, l; f16split(x, h, l);
        h0[j] = h; h1[j] = l;
    }
}

// identity copy-split: in [N,K] -> hi/lo
__global__ void wp_id(const float* __restrict__ in, __half* __restrict__ h0,
                      __half* __restrict__ h1, int n)
{
    for (int j = blockIdx.x * blockDim.x + threadIdx.x; j < n;
         j += gridDim.x * blockDim.x) {
        __half h, l; f16split(in[j], h, l);
        h0[j] = h; h1[j] = l;
    }
}

__global__ void cnorm_k(const float* __restrict__ cb, float* __restrict__ cnorm)
{
    const int k = blockIdx.x;
    float s = 0.0f;
    for (int d = threadIdx.x; d < 512; d += 128) {
        const float v = cb[k * 512 + d];
        s += v * v;
    }
    __shared__ float sh[128];
    sh[threadIdx.x] = s;
    __syncthreads();
    for (int st = 64; st > 0; st >>= 1) {
        if (threadIdx.x < st) sh[threadIdx.x] += sh[threadIdx.x + st];
        __syncthreads();
    }
    if (threadIdx.x == 0) cnorm[k] = sh[0];
}

__global__ void zero_all(float* stats, float* loss, int* cnt)
{
    const int i = blockIdx.x * blockDim.x + threadIdx.x;
    if (i < 6 * 2 * 512) stats[i] = 0.0f;
    if (i < 512) cnt[i] = 0;
    if (i == 0) loss[0] = 0.0f;
}

// ======================= BatchNorm(+ReLU) ===================================
__global__ void bn_stats(const float* __restrict__ X, int M,
                         float* __restrict__ gsum, float* __restrict__ gssq)
{
    const int lane = threadIdx.x & 31;
    const int ry   = threadIdx.x >> 5;
    const int c    = blockIdx.x * 32 + lane;
    const int rend = min(M, (int)(blockIdx.y + 1) * 128);
    float s = 0.0f, ss = 0.0f;
    for (int r = blockIdx.y * 128 + ry; r < rend; r += 8) {
        const float v = X[(long)r * 512 + c];
        s += v; ss += v * v;
    }
    __shared__ float shs[8][32], shq[8][32];
    shs[ry][lane] = s; shq[ry][lane] = ss;
    __syncthreads();
    if (ry == 0) {
        #pragma unroll
        for (int i = 1; i < 8; i++) { s += shs[i][lane]; ss += shq[i][lane]; }
        atomicAdd(&gsum[c], s);
        atomicAdd(&gssq[c], ss);
    }
}

__global__ void bn_norm2(float* __restrict__ X,
                         const float* __restrict__ gamma, const float* __restrict__ beta,
                         const float* __restrict__ gsum, const float* __restrict__ gssq,
                         int M)
{
    const float invM = 1.0f / (float)M;
    const int total = M * 512;
    for (int i = blockIdx.x * blockDim.x + threadIdx.x; i < total;
         i += gridDim.x * blockDim.x) {
        const int c  = i & 511;
        const float mn = gsum[c] * invM;
        const float vr = gssq[c] * invM - mn * mn;
        const float v  = (X[i] - mn) * rsqrtf(vr + EPSV) * gamma[c] + beta[c];
        X[i] = v > 0.0f ? v : 0.0f;
    }
}

// ======================= vector quantization ================================
__global__ void vq_argmin(const float* __restrict__ scores, const float* __restrict__ cnorm,
                          const float* __restrict__ cb, float* __restrict__ q,
                          int* __restrict__ counts)
{
    const int n = blockIdx.x;
    const int k = threadIdx.x;
    const float d = cnorm[k] - 2.0f * scores[(long)n * 512 + k];
    __shared__ float sv[512];
    __shared__ int   si[512];
    sv[k] = d; si[k] = k;
    __syncthreads();
    for (int st = 256; st > 0; st >>= 1) {
        if (k < st) {
            const float ov = sv[k + st];
            const int   oi = si[k + st];
            if (ov < sv[k] || (ov == sv[k] && oi < si[k])) { sv[k] = ov; si[k] = oi; }
        }
        __syncthreads();
    }
    const int best = si[0];
    if (k == 0) atomicAdd(&counts[best], 1);
    q[(long)n * 512 + k] = cb[(long)best * 512 + k];
}

__global__ void vq_loss_k(const float* __restrict__ q, const float* __restrict__ z,
                          float* __restrict__ loss)
{
    float s = 0.0f;
    const int total = 1024 * 512;
    for (int i = blockIdx.x * blockDim.x + threadIdx.x; i < total;
         i += gridDim.x * blockDim.x) {
        const float d = q[i] - z[i];
        s += d * d;
    }
    #pragma unroll
    for (int o = 16; o > 0; o >>= 1) s += __shfl_down_sync(0xffffffffu, s, o);
    __shared__ float sh[8];
    if ((threadIdx.x & 31) == 0) sh[threadIdx.x >> 5] = s;
    __syncthreads();
    if (threadIdx.x < 8) {
        float t = sh[threadIdx.x];
        #pragma unroll
        for (int o = 4; o > 0; o >>= 1) t += __shfl_down_sync(0xffu, t, o);
        if (threadIdx.x == 0) atomicAdd(loss, t);
    }
}

__global__ void finalize_k(const int* __restrict__ counts, const float* __restrict__ loss,
                           float* __restrict__ out, long outsize)
{
    const int k = threadIdx.x;
    const float p = (float)counts[k] * (1.0f / 1024.0f);
    __shared__ float sh[512];
    sh[k] = p * logf(p + 1e-10f);
    __syncthreads();
    for (int st = 256; st > 0; st >>= 1) {
        if (k < st) sh[k] += sh[k + st];
        __syncthreads();
    }
    if (k == 0) {
        const long R = 1024L * 30 * 135;
        if (outsize >= R + 2) {
            out[R]     = loss[0] * 1.25f / (1024.0f * 512.0f);
            out[R + 1] = expf(-sh[0]);
        }
    }
}

// ======================= host launch ========================================
static inline dim3 ggrid(int M, int N)
{
    return dim3((N + 127) / 128, (M + 127) / 128);
}

static void run_bn(float* X, const float* g, const float* b, int M, float* stats, int layer)
{
    float* sum = stats + layer * 1024;
    float* ssq = sum + 512;
    dim3 gs(16, (M + 127) / 128);
    bn_stats<<<gs, 256>>>(X, M, sum, ssq);
    bn_norm2<<<(M * 512 + 255) / 256 < 2048 ? (M * 512 + 255) / 256 : 2048, 256>>>(
        X, g, b, sum, ssq, M);
}

extern "C" void kernel_launch(void* const* d_in, const int* in_sizes, int n_in,
                              void* d_out, int out_size)
{
    (void)in_sizes; (void)n_in;
    float* buf = nullptr;
    __half* hb = nullptr;
    cudaGetSymbolAddress((void**)&buf, g_buf);
    cudaGetSymbolAddress((void**)&hb, g_hbuf);
    cudaFuncSetAttribute(gemm_h3, cudaFuncAttributeMaxDynamicSharedMemorySize, DSMEM);

    const float* input = (const float*)d_in[0];
    const float* W_in  = (const float*)d_in[1];
    const float* b_in  = (const float*)d_in[2];
    const float* w_e1  = (const float*)d_in[3];
    const float* g_e1  = (const float*)d_in[4];
    const float* b_e1  = (const float*)d_in[5];
    const float* w_e2  = (const float*)d_in[6];
    const float* g_e2  = (const float*)d_in[7];
    const float* b_e2  = (const float*)d_in[8];
    const float* w_e3  = (const float*)d_in[9];
    const float* g_e3  = (const float*)d_in[10];
    const float* b_e3  = (const float*)d_in[11];
    const float* cb    = (const float*)d_in[12];
    const float* W_q   = (const float*)d_in[13];
    const float* b_q   = (const float*)d_in[14];
    const float* w_d1  = (const float*)d_in[15];
    const float* g_d1  = (const float*)d_in[16];
    const float* b_d1  = (const float*)d_in[17];
    const float* w_d2  = (const float*)d_in[18];
    const float* g_d2  = (const float*)d_in[19];
    const float* b_d2  = (const float*)d_in[20];
    const float* w_d3  = (const float*)d_in[21];
    const float* g_d3  = (const float*)d_in[22];
    const float* b_d3  = (const float*)d_in[23];
    const float* W_out = (const float*)d_in[24];
    const float* b_out = (const float*)d_in[25];

    float* x0   = buf + O_X0;
    float* e1   = buf + O_E1;
    float* e2   = buf + O_E2;
    float* z    = buf + O_Z;
    float* q    = buf + O_Q;
    float* d0   = buf + O_D0;
    float* d1   = buf + O_D1;
    float* d2   = buf + O_D2;
    float* d3   = buf + O_D3;
    float* sc   = buf + O_SC;
    float* cn   = buf + O_CN;
    float* stats= buf + O_STAT;
    float* loss = buf + O_LOSS;
    int*   cnt  = (int*)(buf + O_CNT);

    __half* we1_0 = hb + H_WE1; __half* we1_1 = we1_0 + 512L * 2560;
    __half* we2_0 = hb + H_WE2; __half* we2_1 = we2_0 + 512L * 1536;
    __half* we3_0 = hb + H_WE3; __half* we3_1 = we3_0 + 512L * 1024;
    __half* wd1_0 = hb + H_WD1; __half* wd1_1 = wd1_0 + 1024L * 512;
    __half* wd2_0 = hb + H_WD2; __half* wd2_1 = wd2_0 + 1536L * 512;
    __half* wd3_0 = hb + H_WD3; __half* wd3_1 = wd3_0 + 2560L * 512;
    __half* wit_0 = hb + H_WIT; __half* wit_1 = wit_0 + 512L * 160;
    __half* wqt_0 = hb + H_WQT; __half* wqt_1 = wqt_0 + 512L * 512;
    __half* wot_0 = hb + H_WOT; __half* wot_1 = wot_0 + 135L * 512;
    __half* cb_0  = hb + H_CB;  __half* cb_1  = cb_0  + 512L * 512;

    float* out = (float*)d_out;

    // ---- prep ----
    zero_all<<<24, 256>>>(stats, loss, cnt);
    wp_enc<<<512, 256>>>(w_e1, we1_0, we1_1, 512, 512, 5, 2560);
    wp_enc<<<384, 256>>>(w_e2, we2_0, we2_1, 512, 512, 3, 1536);
    wp_enc<<<256, 256>>>(w_e3, we3_0, we3_1, 512, 512, 2, 1024);
    wp_dec<<<256, 256>>>(w_d1, wd1_0, wd1_1, 512, 512, 2);
    wp_dec<<<384, 256>>>(w_d2, wd2_0, wd2_1, 512, 512, 3);
    wp_dec<<<512, 256>>>(w_d3, wd3_0, wd3_1, 512, 512, 5);
    wp_tr<<<128, 256>>>(W_in,  wit_0, wit_1, 135, 512, 160);
    wp_tr<<<256, 256>>>(W_q,   wqt_0, wqt_1, 512, 512, 512);
    wp_tr<<<128, 256>>>(W_out, wot_0, wot_1, 512, 135, 512);
    wp_id<<<256, 256>>>(cb, cb_0, cb_1, 512 * 512);
    cnorm_k<<<512, 128>>>(cb, cn);

    // ---- input GEMM: rows (t,b), K=135 -> 512, permuted to [b,t,c] ----
    gemm_h3<<<ggrid(30720, 512), 256, DSMEM>>>(input, wit_0, wit_1, b_in, x0,
                                               30720, 512, 135, 160, 1);

    // ---- encoder ----
    gemm_h3<<<ggrid(6144, 512), 256, DSMEM>>>(x0, we1_0, we1_1, nullptr, e1,
                                              6144, 512, 2560, 2560, 0);
    run_bn(e1, g_e1, b_e1, 6144, stats, 0);

    gemm_h3<<<ggrid(2048, 512), 256, DSMEM>>>(e1, we2_0, we2_1, nullptr, e2,
                                              2048, 512, 1536, 1536, 0);
    run_bn(e2, g_e2, b_e2, 2048, stats, 1);

    gemm_h3<<<ggrid(1024, 512), 256, DSMEM>>>(e2, we3_0, we3_1, nullptr, z,
                                              1024, 512, 1024, 1024, 0);
    run_bn(z, g_e3, b_e3, 1024, stats, 2);

    // ---- vector quantization ----
    gemm_h3<<<ggrid(1024, 512), 256, DSMEM>>>(z, cb_0, cb_1, nullptr, sc,
                                              1024, 512, 512, 512, 0);
    vq_argmin<<<1024, 512>>>(sc, cn, cb, q, cnt);
    vq_loss_k<<<256, 256>>>(q, z, loss);

    // ---- decoder ----
    gemm_h3<<<ggrid(1024, 512), 256, DSMEM>>>(q, wqt_0, wqt_1, b_q, d0,
                                              1024, 512, 512, 512, 0);

    gemm_h3<<<ggrid(1024, 1024), 256, DSMEM>>>(d0, wd1_0, wd1_1, nullptr, d1,
                                               1024, 1024, 512, 512, 0);
    run_bn(d1, g_d1, b_d1, 2048, stats, 3);

    gemm_h3<<<ggrid(2048, 1536), 256, DSMEM>>>(d1, wd2_0, wd2_1, nullptr, d2,
                                               2048, 1536, 512, 512, 0);
    run_bn(d2, g_d2, b_d2, 6144, stats, 4);

    gemm_h3<<<ggrid(6144, 2560), 256, DSMEM>>>(d2, wd3_0, wd3_1, nullptr, d3,
                                               6144, 2560, 512, 512, 0);
    run_bn(d3, g_d3, b_d3, 30720, stats, 5);

    // ---- output GEMM -> recon ----
    gemm_h3<<<ggrid(30720, 135), 256, DSMEM>>>(d3, wot_0, wot_1, b_out, out,
                                               30720, 135, 512, 512, 0);

    // ---- scalars ----
    finalize_k<<<1, 512>>>(cnt, loss, out, (long)out_size);
}

// round 8
// speedup vs baseline: 2.2706x; 1.0321x over previous
#include <cuda_runtime.h>
#include <cuda_fp16.h>
#include <math.h>
#include <stdint.h>

// ---------------------------------------------------------------------------
// VQ-VAE forward. T=30, B=1024, D_POSE=135, H=512, K_CODES=512.
// Activations stored [b, position, channel] -> every conv/convT/linear is a
// plain row-major GEMM: C[M,N] = A[M,K] * B'[N,K]^T.
// GEMMs: mma.sync.m16n8k16 f16, 3xFP16 hi/lo split (err ~2^-24).
// ALL operands (activations and weights) live in gmem as pre-split f16
// pairs, so the GEMM mainloop is pure cp.async + ldmatrix + mma.
// ---------------------------------------------------------------------------

#define EPSV 1e-5f

// ======================= fp32 scratch ======================================
constexpr long O_E1R = 0;                        // 6144 x 512 (raw, pre-BN)
constexpr long O_E2R = O_E1R + 6144L * 512;      // 2048 x 512
constexpr long O_ZR  = O_E2R + 2048L * 512;      // 1024 x 512
constexpr long O_Z   = O_ZR  + 1024L * 512;      // 1024 x 512 (normalized)
constexpr long O_Q   = O_Z   + 1024L * 512;      // 1024 x 512
constexpr long O_D1R = O_Q   + 1024L * 512;      // 1024 x 1024
constexpr long O_D2R = O_D1R + 1024L * 1024;     // 2048 x 1536
constexpr long O_D3R = O_D2R + 2048L * 1536;     // 6144 x 2560
constexpr long O_SC  = O_D3R + 6144L * 2560;     // 1024 x 512
constexpr long O_CN  = O_SC  + 1024L * 512;      // 512
constexpr long O_STAT= O_CN  + 512;              // 6 x 2 x 512
constexpr long O_LOSS= O_STAT+ 6L * 2 * 512;
constexpr long O_CNT = O_LOSS+ 512;
constexpr long TOTALF= O_CNT + 512;

__device__ float g_buf[TOTALF];

// ======================= f16 split scratch (hi then lo per buffer) =========
constexpr long H_WE1 = 0;                          // [512,2560]
constexpr long H_WE2 = H_WE1 + 2L * 512 * 2560;    // [512,1536]
constexpr long H_WE3 = H_WE2 + 2L * 512 * 1536;    // [512,1024]
constexpr long H_WD1 = H_WE3 + 2L * 512 * 1024;    // [1024,512]
constexpr long H_WD2 = H_WD1 + 2L * 1024 * 512;    // [1536,512]
constexpr long H_WD3 = H_WD2 + 2L * 1536 * 512;    // [2560,512]
constexpr long H_WIT = H_WD3 + 2L * 2560 * 512;    // [512,160]
constexpr long H_WQT = H_WIT + 2L * 512 * 160;     // [512,512]
constexpr long H_WOT = H_WQT + 2L * 512 * 512;     // [135,512]
constexpr long H_CB  = H_WOT + 2L * 135 * 512;     // [512,512]
constexpr long H_XIN = H_CB  + 2L * 512 * 512;     // [30720,160]
constexpr long H_X0  = H_XIN + 2L * 30720 * 160;   // [30720,512]
constexpr long H_E1  = H_X0  + 2L * 30720 * 512;   // [6144,512]
constexpr long H_E2  = H_E1  + 2L * 6144 * 512;    // [2048,512]
constexpr long H_Z   = H_E2  + 2L * 2048 * 512;    // [1024,512]
constexpr long H_Q   = H_Z   + 2L * 1024 * 512;    // [1024,512]
constexpr long H_D0  = H_Q   + 2L * 1024 * 512;    // [1024,512]
constexpr long H_D1  = H_D0  + 2L * 1024 * 512;    // [1024,1024]
constexpr long H_D2  = H_D1  + 2L * 1024 * 1024;   // [2048,1536]
constexpr long H_D3  = H_D2  + 2L * 2048 * 1536;   // [30720,512] (=6144x2560)
constexpr long TOTALH= H_D3  + 2L * 30720 * 512;

__device__ __half g_hbuf[TOTALH];

// ======================= helpers ===========================================
__device__ __forceinline__ uint32_t smem_u32(const void* p)
{
    return (uint32_t)__cvta_generic_to_shared(p);
}

__device__ __forceinline__ void f16split(float x, __half& h, __half& l)
{
    h = __float2half_rn(x);
    l = __float2half_rn(x - __half2float(h));
}

__device__ __forceinline__ void mma_f16(float* c, const uint32_t* a, const uint32_t* b)
{
    asm volatile(
        "mma.sync.aligned.m16n8k16.row.col.f32.f16.f16.f32 "
        "{%0,%1,%2,%3}, {%4,%5,%6,%7}, {%8,%9}, {%0,%1,%2,%3};"
        : "+f"(c[0]), "+f"(c[1]), "+f"(c[2]), "+f"(c[3])
        : "r"(a[0]), "r"(a[1]), "r"(a[2]), "r"(a[3]), "r"(b[0]), "r"(b[1]));
}

__device__ __forceinline__ void ldm4(uint32_t& r0, uint32_t& r1, uint32_t& r2,
                                     uint32_t& r3, uint32_t addr)
{
    asm volatile("ldmatrix.sync.aligned.m8n8.x4.shared.b16 {%0,%1,%2,%3}, [%4];"
                 : "=r"(r0), "=r"(r1), "=r"(r2), "=r"(r3) : "r"(addr));
}

__device__ __forceinline__ void cp16(uint32_t dst, const void* src, int pred)
{
    asm volatile("cp.async.cg.shared.global [%0], [%1], 16, %2;"
                 :: "r"(dst), "l"(src), "r"(pred ? 16 : 0) : "memory");
}
__device__ __forceinline__ void cp_commit()
{
    asm volatile("cp.async.commit_group;" ::: "memory");
}

// ======================= GEMM ==============================================
// CTA tile 128x128, BK=32(halves), 256 threads, 8 warps (4 M x 2 N),
// warp tile 32x64. SMEM row = 32 halves padded to 80B stride.
// Mainloop: cp.async (A0/A1/B0/B1) + ldmatrix + mma only.
// Epilogue: optional f32 store (Cf; vectorized only when N is even) and/or
// split-f16 store (C0/C1).
// perm==1: output row remap r=(t*1024+b) -> b*30+t (input GEMM only).

constexpr int OFF_A0 = 0;
constexpr int OFF_A1 = 128 * 80;          // 10240
constexpr int OFF_B0 = 2 * 128 * 80;      // 20480
constexpr int OFF_B1 = 3 * 128 * 80;      // 30720
constexpr int STAGE  = 4 * 128 * 80;      // 40960
constexpr int DSMEM  = 2 * STAGE + 1024;

__global__ __launch_bounds__(256)
void gemm_hh(const __half* __restrict__ A0, const __half* __restrict__ A1,
             const __half* __restrict__ B0, const __half* __restrict__ B1,
             const float* __restrict__ bias, float* __restrict__ Cf,
             __half* __restrict__ C0, __half* __restrict__ C1,
             int M, int N, int Kp, int perm)
{
    extern __shared__ char dsm[];
    const uint32_t dynb = smem_u32(dsm);
    const uint32_t base = (dynb + 1023u) & ~1023u;

    const int tid  = threadIdx.x;
    const int wid  = tid >> 5;
    const int lane = tid & 31;
    const int wm   = (wid & 3) * 32;
    const int wn   = (wid >> 2) * 64;
    const int g    = lane >> 2;
    const int t    = lane & 3;
    const int m0   = blockIdx.y * 128;
    const int n0   = blockIdx.x * 128;

    const int nk = Kp >> 5;

    // per-thread load coords: 512 chunk-slots per operand buffer, 2 per thread
    const int r0c = (tid + 0)   >> 2, c0c = (tid + 0)   & 3;
    const int r1c = (tid + 256) >> 2, c1c = (tid + 256) & 3;
    const int gmA0 = m0 + r0c, gmA1 = m0 + r1c;
    const int gnB0 = n0 + r0c, gnB1 = n0 + r1c;
    const int okA0 = gmA0 < M, okA1 = gmA1 < M;
    const int okB0 = gnB0 < N, okB1 = gnB1 < N;
    const long aoff0 = (long)(okA0 ? gmA0 : 0) * Kp + c0c * 8;
    const long aoff1 = (long)(okA1 ? gmA1 : 0) * Kp + c1c * 8;
    const long boff0 = (long)(okB0 ? gnB0 : 0) * Kp + c0c * 8;
    const long boff1 = (long)(okB1 ? gnB1 : 0) * Kp + c1c * 8;
    const uint32_t d0a = r0c * 80 + c0c * 16;
    const uint32_t d1a = r1c * 80 + c1c * 16;

    auto issue = [&](int k0, uint32_t stg) {
        cp16(stg + OFF_A0 + d0a, A0 + aoff0 + k0, okA0);
        cp16(stg + OFF_A0 + d1a, A0 + aoff1 + k0, okA1);
        cp16(stg + OFF_A1 + d0a, A1 + aoff0 + k0, okA0);
        cp16(stg + OFF_A1 + d1a, A1 + aoff1 + k0, okA1);
        cp16(stg + OFF_B0 + d0a, B0 + boff0 + k0, okB0);
        cp16(stg + OFF_B0 + d1a, B0 + boff1 + k0, okB1);
        cp16(stg + OFF_B1 + d0a, B1 + boff0 + k0, okB0);
        cp16(stg + OFF_B1 + d1a, B1 + boff1 + k0, okB1);
        cp_commit();
    };

    float acc[2][8][4];
    #pragma unroll
    for (int a = 0; a < 2; a++)
        #pragma unroll
        for (int b = 0; b < 8; b++)
            #pragma unroll
            for (int c = 0; c < 4; c++) acc[a][b][c] = 0.f;

    issue(0, base);

    for (int it = 0; it < nk; ++it) {
        const int s = it & 1;
        const uint32_t stg_u = base + (uint32_t)s * STAGE;

        if (it + 1 < nk) {
            issue((it + 1) << 5, base + (uint32_t)(s ^ 1) * STAGE);
            asm volatile("cp.async.wait_group 1;" ::: "memory");
        } else {
            asm volatile("cp.async.wait_group 0;" ::: "memory");
        }
        __syncthreads();

        // ---- compute: 2 k16 steps ----
        #pragma unroll
        for (int ks = 0; ks < 2; ++ks) {
            uint32_t aH[2][4], aL[2][4];
            {
                const int arw = (lane & 15);
                const int kwo = ks * 8 + (lane >> 4) * 4;
                #pragma unroll
                for (int mt = 0; mt < 2; ++mt) {
                    const uint32_t ad = stg_u + (wm + mt * 16 + arw) * 80 + kwo * 4;
                    ldm4(aH[mt][0], aH[mt][1], aH[mt][2], aH[mt][3], ad + OFF_A0);
                    ldm4(aL[mt][0], aL[mt][1], aL[mt][2], aL[mt][3], ad + OFF_A1);
                }
            }
            const int brw = (lane >> 4) * 8 + (lane & 7);
            const int bkw = ks * 8 + ((lane >> 3) & 1) * 4;
            #pragma unroll
            for (int p = 0; p < 4; ++p) {
                uint32_t bH[4], bL[4];
                const uint32_t bd = stg_u + (wn + p * 16 + brw) * 80 + bkw * 4;
                ldm4(bH[0], bH[1], bH[2], bH[3], bd + OFF_B0);
                ldm4(bL[0], bL[1], bL[2], bL[3], bd + OFF_B1);
                #pragma unroll
                for (int sub = 0; sub < 2; ++sub) {
                    const int nt = 2 * p + sub;
                    uint32_t b_h[2] = {bH[sub * 2], bH[sub * 2 + 1]};
                    uint32_t b_l[2] = {bL[sub * 2], bL[sub * 2 + 1]};
                    #pragma unroll
                    for (int mt = 0; mt < 2; ++mt) {
                        mma_f16(acc[mt][nt], aH[mt], b_h);
                        mma_f16(acc[mt][nt], aH[mt], b_l);
                        mma_f16(acc[mt][nt], aL[mt], b_h);
                    }
                }
            }
        }
        __syncthreads();
    }

    // ---- epilogue ----
    const bool neven = ((N & 1) == 0);   // float2/half2 stores only when rows stay aligned
    #pragma unroll
    for (int mt = 0; mt < 2; ++mt) {
        #pragma unroll
        for (int half = 0; half < 2; ++half) {
            const int gm = m0 + wm + mt * 16 + g + half * 8;
            if (gm >= M) continue;
            const int orow = perm ? ((gm & 1023) * 30 + (gm >> 10)) : gm;
            #pragma unroll
            for (int nt = 0; nt < 8; ++nt) {
                const int col = n0 + wn + nt * 8 + t * 2;
                if (col >= N) continue;
                float v0 = acc[mt][nt][half * 2 + 0];
                float v1 = acc[mt][nt][half * 2 + 1];
                if (bias) {
                    v0 += bias[col];
                    if (col + 1 < N) v1 += bias[col + 1];
                }
                if (Cf) {
                    if (neven && col + 1 < N) {
                        *(float2*)&Cf[(long)orow * N + col] = make_float2(v0, v1);
                    } else {
                        Cf[(long)orow * N + col] = v0;
                        if (col + 1 < N) Cf[(long)orow * N + col + 1] = v1;
                    }
                }
                if (C0 && neven && col + 1 < N) {
                    __half h0, l0, h1, l1;
                    f16split(v0, h0, l0);
                    f16split(v1, h1, l1);
                    *(__half2*)&C0[(long)orow * N + col] = __halves2half2(h0, h1);
                    *(__half2*)&C1[(long)orow * N + col] = __halves2half2(l0, l1);
                }
            }
        }
    }
}

// ======================= weight / input prep ================================
// encoder: B'[o][k*I+i] = w[o,i,k]; stored [O][Kp] hi/lo
__global__ void wp_enc(const float* __restrict__ w, __half* __restrict__ h0,
                       __half* __restrict__ h1, int I, int O, int Kk, int Kp)
{
    const int Ke = I * Kk;
    const int n  = O * Kp;
    for (int j = blockIdx.x * blockDim.x + threadIdx.x; j < n;
         j += gridDim.x * blockDim.x) {
        const int o  = j / Kp;
        const int kk = j % Kp;
        float x = 0.f;
        if (kk < Ke) {
            const int i = kk % I;
            const int k = kk / I;
            x = w[(long)o * Ke + (long)i * Kk + k];
        }
        __half h, l; f16split(x, h, l);
        h0[j] = h; h1[j] = l;
    }
}

// decoder: B'[(k*O+o)][i] = w[i,o,k]
__global__ void wp_dec(const float* __restrict__ w, __half* __restrict__ h0,
                       __half* __restrict__ h1, int I, int O, int Kk)
{
    const int n = Kk * O * I;
    for (int j = blockIdx.x * blockDim.x + threadIdx.x; j < n;
         j += gridDim.x * blockDim.x) {
        const int i  = j % I;
        const int nn = j / I;
        const int o  = nn % O;
        const int k  = nn / O;
        const float x = w[(long)i * O * Kk + (long)o * Kk + k];
        __half h, l; f16split(x, h, l);
        h0[j] = h; h1[j] = l;
    }
}

// transpose-split: in [R,C] -> out [C][Kp] (K=R), zero-pad
__global__ void wp_tr(const float* __restrict__ in, __half* __restrict__ h0,
                      __half* __restrict__ h1, int R, int C, int Kp)
{
    const int n = C * Kp;
    for (int j = blockIdx.x * blockDim.x + threadIdx.x; j < n;
         j += gridDim.x * blockDim.x) {
        const int c = j / Kp;
        const int r = j % Kp;
        const float x = (r < R) ? in[(long)r * C + c] : 0.f;
        __half h, l; f16split(x, h, l);
        h0[j] = h; h1[j] = l;
    }
}

// identity split: in [N,K]
__global__ void wp_id(const float* __restrict__ in, __half* __restrict__ h0,
                      __half* __restrict__ h1, int n)
{
    for (int j = blockIdx.x * blockDim.x + threadIdx.x; j < n;
         j += gridDim.x * blockDim.x) {
        __half h, l; f16split(in[j], h, l);
        h0[j] = h; h1[j] = l;
    }
}

// row-pad split: in [R,C] -> out [R,Kp]
__global__ void wp_in(const float* __restrict__ in, __half* __restrict__ h0,
                      __half* __restrict__ h1, int R, int C, int Kp)
{
    const long n = (long)R * Kp;
    for (long j = blockIdx.x * blockDim.x + threadIdx.x; j < n;
         j += (long)gridDim.x * blockDim.x) {
        const long r = j / Kp;
        const int  c = (int)(j % Kp);
        const float x = (c < C) ? in[r * C + c] : 0.f;
        __half h, l; f16split(x, h, l);
        h0[j] = h; h1[j] = l;
    }
}

__global__ void cnorm_k(const float* __restrict__ cb, float* __restrict__ cnorm)
{
    const int k = blockIdx.x;
    float s = 0.0f;
    for (int d = threadIdx.x; d < 512; d += 128) {
        const float v = cb[k * 512 + d];
        s += v * v;
    }
    __shared__ float sh[128];
    sh[threadIdx.x] = s;
    __syncthreads();
    for (int st = 64; st > 0; st >>= 1) {
        if (threadIdx.x < st) sh[threadIdx.x] += sh[threadIdx.x + st];
        __syncthreads();
    }
    if (threadIdx.x == 0) cnorm[k] = sh[0];
}

__global__ void zero_all(float* stats, float* loss, int* cnt)
{
    const int i = blockIdx.x * blockDim.x + threadIdx.x;
    if (i < 6 * 2 * 512) stats[i] = 0.0f;
    if (i < 512) cnt[i] = 0;
    if (i == 0) loss[0] = 0.0f;
}

// ======================= BatchNorm(+ReLU) ===================================
__global__ void bn_stats(const float* __restrict__ X, int M,
                         float* __restrict__ gsum, float* __restrict__ gssq)
{
    const int lane = threadIdx.x & 31;
    const int ry   = threadIdx.x >> 5;
    const int c    = blockIdx.x * 32 + lane;
    const int rend = min(M, (int)(blockIdx.y + 1) * 128);
    float s = 0.0f, ss = 0.0f;
    for (int r = blockIdx.y * 128 + ry; r < rend; r += 8) {
        const float v = X[(long)r * 512 + c];
        s += v; ss += v * v;
    }
    __shared__ float shs[8][32], shq[8][32];
    shs[ry][lane] = s; shq[ry][lane] = ss;
    __syncthreads();
    if (ry == 0) {
        #pragma unroll
        for (int i = 1; i < 8; i++) { s += shs[i][lane]; ss += shq[i][lane]; }
        atomicAdd(&gsum[c], s);
        atomicAdd(&gssq[c], ss);
    }
}

// normalize + ReLU; write split f16 (and optional f32 copy)
__global__ void bn_norm2(const float* __restrict__ X,
                         const float* __restrict__ gamma, const float* __restrict__ beta,
                         const float* __restrict__ gsum, const float* __restrict__ gssq,
                         int M, __half* __restrict__ h0, __half* __restrict__ h1,
                         float* __restrict__ fout)
{
    const float invM = 1.0f / (float)M;
    const int total = M * 512;
    for (int i = blockIdx.x * blockDim.x + threadIdx.x; i < total;
         i += gridDim.x * blockDim.x) {
        const int c  = i & 511;
        const float mn = gsum[c] * invM;
        const float vr = gssq[c] * invM - mn * mn;
        float v = (X[i] - mn) * rsqrtf(vr + EPSV) * gamma[c] + beta[c];
        v = v > 0.0f ? v : 0.0f;
        __half h, l; f16split(v, h, l);
        h0[i] = h; h1[i] = l;
        if (fout) fout[i] = v;
    }
}

// ======================= vector quantization ================================
// argmin + quantized copy (f32 + split f16) + counts + sum((q-z)^2)
__global__ void vq_argmin(const float* __restrict__ scores, const float* __restrict__ cnorm,
                          const float* __restrict__ cb,
                          const __half* __restrict__ cb0, const __half* __restrict__ cb1,
                          const float* __restrict__ z,
                          float* __restrict__ q, __half* __restrict__ qh,
                          __half* __restrict__ ql,
                          int* __restrict__ counts, float* __restrict__ loss)
{
    const int n = blockIdx.x;
    const int k = threadIdx.x;
    const float d = cnorm[k] - 2.0f * scores[(long)n * 512 + k];
    __shared__ float sv[512];
    __shared__ int   si[512];
    sv[k] = d; si[k] = k;
    __syncthreads();
    for (int st = 256; st > 0; st >>= 1) {
        if (k < st) {
            const float ov = sv[k + st];
            const int   oi = si[k + st];
            if (ov < sv[k] || (ov == sv[k] && oi < si[k])) { sv[k] = ov; si[k] = oi; }
        }
        __syncthreads();
    }
    const int best = si[0];
    __syncthreads();

    const float val = cb[(long)best * 512 + k];
    q [(long)n * 512 + k] = val;
    qh[(long)n * 512 + k] = cb0[(long)best * 512 + k];
    ql[(long)n * 512 + k] = cb1[(long)best * 512 + k];

    const float diff = val - z[(long)n * 512 + k];
    sv[k] = diff * diff;
    __syncthreads();
    for (int st = 256; st > 0; st >>= 1) {
        if (k < st) sv[k] += sv[k + st];
        __syncthreads();
    }
    if (k == 0) {
        atomicAdd(&counts[best], 1);
        atomicAdd(loss, sv[0]);
    }
}

__global__ void finalize_k(const int* __restrict__ counts, const float* __restrict__ loss,
                           float* __restrict__ out, long outsize)
{
    const int k = threadIdx.x;
    const float p = (float)counts[k] * (1.0f / 1024.0f);
    __shared__ float sh[512];
    sh[k] = p * logf(p + 1e-10f);
    __syncthreads();
    for (int st = 256; st > 0; st >>= 1) {
        if (k < st) sh[k] += sh[k + st];
        __syncthreads();
    }
    if (k == 0) {
        const long R = 1024L * 30 * 135;
        if (outsize >= R + 2) {
            out[R]     = loss[0] * 1.25f / (1024.0f * 512.0f);
            out[R + 1] = expf(-sh[0]);
        }
    }
}

// ======================= host launch ========================================
static inline dim3 ggrid(int M, int N)
{
    return dim3((N + 127) / 128, (M + 127) / 128);
}

static void run_bn(const float* X, const float* g, const float* b, int M,
                   float* stats, int layer, __half* h0, __half* h1, float* fout)
{
    float* sum = stats + layer * 1024;
    float* ssq = sum + 512;
    dim3 gs(16, (M + 127) / 128);
    bn_stats<<<gs, 256>>>(X, M, sum, ssq);
    int nb = (M * 512 + 255) / 256; if (nb > 2048) nb = 2048;
    bn_norm2<<<nb, 256>>>(X, g, b, sum, ssq, M, h0, h1, fout);
}

extern "C" void kernel_launch(void* const* d_in, const int* in_sizes, int n_in,
                              void* d_out, int out_size)
{
    (void)in_sizes; (void)n_in;
    float* buf = nullptr;
    __half* hb = nullptr;
    cudaGetSymbolAddress((void**)&buf, g_buf);
    cudaGetSymbolAddress((void**)&hb, g_hbuf);
    cudaFuncSetAttribute(gemm_hh, cudaFuncAttributeMaxDynamicSharedMemorySize, DSMEM);

    const float* input = (const float*)d_in[0];
    const float* W_in  = (const float*)d_in[1];
    const float* b_in  = (const float*)d_in[2];
    const float* w_e1  = (const float*)d_in[3];
    const float* g_e1  = (const float*)d_in[4];
    const float* b_e1  = (const float*)d_in[5];
    const float* w_e2  = (const float*)d_in[6];
    const float* g_e2  = (const float*)d_in[7];
    const float* b_e2  = (const float*)d_in[8];
    const float* w_e3  = (const float*)d_in[9];
    const float* g_e3  = (const float*)d_in[10];
    const float* b_e3  = (const float*)d_in[11];
    const float* cb    = (const float*)d_in[12];
    const float* W_q   = (const float*)d_in[13];
    const float* b_q   = (const float*)d_in[14];
    const float* w_d1  = (const float*)d_in[15];
    const float* g_d1  = (const float*)d_in[16];
    const float* b_d1  = (const float*)d_in[17];
    const float* w_d2  = (const float*)d_in[18];
    const float* g_d2  = (const float*)d_in[19];
    const float* b_d2  = (const float*)d_in[20];
    const float* w_d3  = (const float*)d_in[21];
    const float* g_d3  = (const float*)d_in[22];
    const float* b_d3  = (const float*)d_in[23];
    const float* W_out = (const float*)d_in[24];
    const float* b_out = (const float*)d_in[25];

    float* e1r  = buf + O_E1R;
    float* e2r  = buf + O_E2R;
    float* zr   = buf + O_ZR;
    float* z    = buf + O_Z;
    float* q    = buf + O_Q;
    float* d1r  = buf + O_D1R;
    float* d2r  = buf + O_D2R;
    float* d3r  = buf + O_D3R;
    float* sc   = buf + O_SC;
    float* cn   = buf + O_CN;
    float* stats= buf + O_STAT;
    float* loss = buf + O_LOSS;
    int*   cnt  = (int*)(buf + O_CNT);

    __half* we1_0 = hb + H_WE1; __half* we1_1 = we1_0 + 512L * 2560;
    __half* we2_0 = hb + H_WE2; __half* we2_1 = we2_0 + 512L * 1536;
    __half* we3_0 = hb + H_WE3; __half* we3_1 = we3_0 + 512L * 1024;
    __half* wd1_0 = hb + H_WD1; __half* wd1_1 = wd1_0 + 1024L * 512;
    __half* wd2_0 = hb + H_WD2; __half* wd2_1 = wd2_0 + 1536L * 512;
    __half* wd3_0 = hb + H_WD3; __half* wd3_1 = wd3_0 + 2560L * 512;
    __half* wit_0 = hb + H_WIT; __half* wit_1 = wit_0 + 512L * 160;
    __half* wqt_0 = hb + H_WQT; __half* wqt_1 = wqt_0 + 512L * 512;
    __half* wot_0 = hb + H_WOT; __half* wot_1 = wot_0 + 135L * 512;
    __half* cb_0  = hb + H_CB;  __half* cb_1  = cb_0  + 512L * 512;
    __half* xin_0 = hb + H_XIN; __half* xin_1 = xin_0 + 30720L * 160;
    __half* x0_0  = hb + H_X0;  __half* x0_1  = x0_0  + 30720L * 512;
    __half* e1_0  = hb + H_E1;  __half* e1_1  = e1_0  + 6144L * 512;
    __half* e2_0  = hb + H_E2;  __half* e2_1  = e2_0  + 2048L * 512;
    __half* z_0   = hb + H_Z;   __half* z_1   = z_0   + 1024L * 512;
    __half* q_0   = hb + H_Q;   __half* q_1   = q_0   + 1024L * 512;
    __half* d0_0  = hb + H_D0;  __half* d0_1  = d0_0  + 1024L * 512;
    __half* d1_0  = hb + H_D1;  __half* d1_1  = d1_0  + 1024L * 1024;
    __half* d2_0  = hb + H_D2;  __half* d2_1  = d2_0  + 2048L * 1536;
    __half* d3_0  = hb + H_D3;  __half* d3_1  = d3_0  + 30720L * 512;

    float* out = (float*)d_out;

    // ---- prep ----
    zero_all<<<24, 256>>>(stats, loss, cnt);
    wp_enc<<<512, 256>>>(w_e1, we1_0, we1_1, 512, 512, 5, 2560);
    wp_enc<<<384, 256>>>(w_e2, we2_0, we2_1, 512, 512, 3, 1536);
    wp_enc<<<256, 256>>>(w_e3, we3_0, we3_1, 512, 512, 2, 1024);
    wp_dec<<<256, 256>>>(w_d1, wd1_0, wd1_1, 512, 512, 2);
    wp_dec<<<384, 256>>>(w_d2, wd2_0, wd2_1, 512, 512, 3);
    wp_dec<<<512, 256>>>(w_d3, wd3_0, wd3_1, 512, 512, 5);
    wp_tr<<<128, 256>>>(W_in,  wit_0, wit_1, 135, 512, 160);
    wp_tr<<<256, 256>>>(W_q,   wqt_0, wqt_1, 512, 512, 512);
    wp_tr<<<128, 256>>>(W_out, wot_0, wot_1, 512, 135, 512);
    wp_id<<<256, 256>>>(cb, cb_0, cb_1, 512 * 512);
    wp_in<<<2048, 256>>>(input, xin_0, xin_1, 30720, 135, 160);
    cnorm_k<<<512, 128>>>(cb, cn);

    // ---- input GEMM: K=135(pad160) -> 512, output split-only, perm ----
    gemm_hh<<<ggrid(30720, 512), 256, DSMEM>>>(
        xin_0, xin_1, wit_0, wit_1, b_in, nullptr, x0_0, x0_1, 30720, 512, 160, 1);

    // ---- encoder ----
    gemm_hh<<<ggrid(6144, 512), 256, DSMEM>>>(
        x0_0, x0_1, we1_0, we1_1, nullptr, e1r, nullptr, nullptr, 6144, 512, 2560, 0);
    run_bn(e1r, g_e1, b_e1, 6144, stats, 0, e1_0, e1_1, nullptr);

    gemm_hh<<<ggrid(2048, 512), 256, DSMEM>>>(
        e1_0, e1_1, we2_0, we2_1, nullptr, e2r, nullptr, nullptr, 2048, 512, 1536, 0);
    run_bn(e2r, g_e2, b_e2, 2048, stats, 1, e2_0, e2_1, nullptr);

    gemm_hh<<<ggrid(1024, 512), 256, DSMEM>>>(
        e2_0, e2_1, we3_0, we3_1, nullptr, zr, nullptr, nullptr, 1024, 512, 1024, 0);
    run_bn(zr, g_e3, b_e3, 1024, stats, 2, z_0, z_1, z);

    // ---- vector quantization ----
    gemm_hh<<<ggrid(1024, 512), 256, DSMEM>>>(
        z_0, z_1, cb_0, cb_1, nullptr, sc, nullptr, nullptr, 1024, 512, 512, 0);
    vq_argmin<<<1024, 512>>>(sc, cn, cb, cb_0, cb_1, z, q, q_0, q_1, cnt, loss);

    // ---- decoder ----
    gemm_hh<<<ggrid(1024, 512), 256, DSMEM>>>(
        q_0, q_1, wqt_0, wqt_1, b_q, nullptr, d0_0, d0_1, 1024, 512, 512, 0);

    gemm_hh<<<ggrid(1024, 1024), 256, DSMEM>>>(
        d0_0, d0_1, wd1_0, wd1_1, nullptr, d1r, nullptr, nullptr, 1024, 1024, 512, 0);
    run_bn(d1r, g_d1, b_d1, 2048, stats, 3, d1_0, d1_1, nullptr);

    gemm_hh<<<ggrid(2048, 1536), 256, DSMEM>>>(
        d1_0, d1_1, wd2_0, wd2_1, nullptr, d2r, nullptr, nullptr, 2048, 1536, 512, 0);
    run_bn(d2r, g_d2, b_d2, 6144, stats, 4, d2_0, d2_1, nullptr);

    gemm_hh<<<ggrid(6144, 2560), 256, DSMEM>>>(
        d2_0, d2_1, wd3_0, wd3_1, nullptr, d3r, nullptr, nullptr, 6144, 2560, 512, 0);
    run_bn(d3r, g_d3, b_d3, 30720, stats, 5, d3_0, d3_1, nullptr);

    // ---- output GEMM -> recon ----
    gemm_hh<<<ggrid(30720, 135), 256, DSMEM>>>(
        d3_0, d3_1, wot_0, wot_1, b_out, out, nullptr, nullptr, 30720, 135, 512, 0);

    // ---- scalars ----
    finalize_k<<<1, 512>>>(cnt, loss, out, (long)out_size);
}

// round 9
// speedup vs baseline: 2.3998x; 1.0569x over previous
#include <cuda_runtime.h>
#include <cuda_fp16.h>
#include <math.h>
#include <stdint.h>

// ---------------------------------------------------------------------------
// VQ-VAE forward. T=30, B=1024, D_POSE=135, H=512, K_CODES=512.
// Activations [b, position, channel] -> every conv/convT/linear is a row-major
// GEMM C[M,N] = A[M,K] * B'[N,K]^T on mma.sync.m16n8k16 f16 with 3xFP16
// hi/lo split (err ~2^-24). All operands pre-split f16 in gmem; mainloop is
// pure cp.async + ldmatrix + mma. BN stats fused into GEMM epilogue.
// ---------------------------------------------------------------------------

#define EPSV 1e-5f

// ======================= fp32 scratch ======================================
constexpr long O_E1R = 0;                        // 6144 x 512 (raw, pre-BN)
constexpr long O_E2R = O_E1R + 6144L * 512;      // 2048 x 512
constexpr long O_ZR  = O_E2R + 2048L * 512;      // 1024 x 512
constexpr long O_Z   = O_ZR  + 1024L * 512;      // 1024 x 512 (normalized)
constexpr long O_Q   = O_Z   + 1024L * 512;      // 1024 x 512
constexpr long O_D1R = O_Q   + 1024L * 512;      // 1024 x 1024
constexpr long O_D2R = O_D1R + 1024L * 1024;     // 2048 x 1536
constexpr long O_D3R = O_D2R + 2048L * 1536;     // 6144 x 2560
constexpr long O_SC  = O_D3R + 6144L * 2560;     // 1024 x 512
constexpr long O_CN  = O_SC  + 1024L * 512;      // 512
constexpr long O_STAT= O_CN  + 512;              // 6 x 2 x 512
constexpr long O_LOSS= O_STAT+ 6L * 2 * 512;
constexpr long O_CNT = O_LOSS+ 512;
constexpr long TOTALF= O_CNT + 512;

__device__ float g_buf[TOTALF];

// ======================= f16 split scratch (hi then lo per buffer) =========
constexpr long H_WE1 = 0;                          // [512,2560]
constexpr long H_WE2 = H_WE1 + 2L * 512 * 2560;    // [512,1536]
constexpr long H_WE3 = H_WE2 + 2L * 512 * 1536;    // [512,1024]
constexpr long H_WD1 = H_WE3 + 2L * 512 * 1024;    // [1024,512]
constexpr long H_WD2 = H_WD1 + 2L * 1024 * 512;    // [1536,512]
constexpr long H_WD3 = H_WD2 + 2L * 1536 * 512;    // [2560,512]
constexpr long H_WIT = H_WD3 + 2L * 2560 * 512;    // [512,160]
constexpr long H_WQT = H_WIT + 2L * 512 * 160;     // [512,512]
constexpr long H_WOT = H_WQT + 2L * 512 * 512;     // [135,512]
constexpr long H_CB  = H_WOT + 2L * 135 * 512;     // [512,512]
constexpr long H_XIN = H_CB  + 2L * 512 * 512;     // [30720,160]
constexpr long H_X0  = H_XIN + 2L * 30720 * 160;   // [30720,512]
constexpr long H_E1  = H_X0  + 2L * 30720 * 512;   // [6144,512]
constexpr long H_E2  = H_E1  + 2L * 6144 * 512;    // [2048,512]
constexpr long H_Z   = H_E2  + 2L * 2048 * 512;    // [1024,512]
constexpr long H_Q   = H_Z   + 2L * 1024 * 512;    // [1024,512]
constexpr long H_D0  = H_Q   + 2L * 1024 * 512;    // [1024,512]
constexpr long H_D1  = H_D0  + 2L * 1024 * 512;    // [1024,1024]
constexpr long H_D2  = H_D1  + 2L * 1024 * 1024;   // [2048,1536]
constexpr long H_D3  = H_D2  + 2L * 2048 * 1536;   // [30720,512]
constexpr long TOTALH= H_D3  + 2L * 30720 * 512;

__device__ __half g_hbuf[TOTALH];

// ======================= helpers ===========================================
__device__ __forceinline__ uint32_t smem_u32(const void* p)
{
    return (uint32_t)__cvta_generic_to_shared(p);
}

__device__ __forceinline__ void f16split(float x, __half& h, __half& l)
{
    h = __float2half_rn(x);
    l = __float2half_rn(x - __half2float(h));
}

__device__ __forceinline__ void mma_f16(float* c, const uint32_t* a, const uint32_t* b)
{
    asm volatile(
        "mma.sync.aligned.m16n8k16.row.col.f32.f16.f16.f32 "
        "{%0,%1,%2,%3}, {%4,%5,%6,%7}, {%8,%9}, {%0,%1,%2,%3};"
        : "+f"(c[0]), "+f"(c[1]), "+f"(c[2]), "+f"(c[3])
        : "r"(a[0]), "r"(a[1]), "r"(a[2]), "r"(a[3]), "r"(b[0]), "r"(b[1]));
}

__device__ __forceinline__ void ldm4(uint32_t& r0, uint32_t& r1, uint32_t& r2,
                                     uint32_t& r3, uint32_t addr)
{
    asm volatile("ldmatrix.sync.aligned.m8n8.x4.shared.b16 {%0,%1,%2,%3}, [%4];"
                 : "=r"(r0), "=r"(r1), "=r"(r2), "=r"(r3) : "r"(addr));
}

__device__ __forceinline__ void cp16(uint32_t dst, const void* src, int pred)
{
    asm volatile("cp.async.cg.shared.global [%0], [%1], 16, %2;"
                 :: "r"(dst), "l"(src), "r"(pred ? 16 : 0) : "memory");
}
__device__ __forceinline__ void cp_commit()
{
    asm volatile("cp.async.commit_group;" ::: "memory");
}

// ======================= GEMM ==============================================
// Templated CTA tile: (64*MTILES) x 128, BK=32 halves, 256 threads, 8 warps
// (4 M x 2 N), warp tile (16*MTILES) x 64. SMEM row stride 80B (odd 16B
// groups -> conflict-free ldmatrix).
// Mainloop: cp.async + ldmatrix + mma only.
// Epilogue: optional f32 store (vectorized only if N even), optional
// split-f16 store, optional fused BN stats (gsum/gssq atomics, channel=col&511).
// perm==1: output row remap r=(t*1024+b) -> b*30+t.

template<int MTILES>
__global__ __launch_bounds__(256)
void gemm_hh(const __half* __restrict__ A0, const __half* __restrict__ A1,
             const __half* __restrict__ B0, const __half* __restrict__ B1,
             const float* __restrict__ bias, float* __restrict__ Cf,
             __half* __restrict__ C0, __half* __restrict__ C1,
             float* __restrict__ gsum, float* __restrict__ gssq,
             int M, int N, int Kp, int perm)
{
    constexpr int AROWS  = 64 * MTILES;
    constexpr int OFF_A1_ = AROWS * 80;
    constexpr int OFF_B0_ = 2 * AROWS * 80;
    constexpr int OFF_B1_ = OFF_B0_ + 128 * 80;
    constexpr int STG     = OFF_B0_ + 2 * 128 * 80;

    extern __shared__ char dsm[];
    const uint32_t dynb = smem_u32(dsm);
    const uint32_t base = (dynb + 1023u) & ~1023u;
    char* smg = dsm + (base - dynb);

    const int tid  = threadIdx.x;
    const int wid  = tid >> 5;
    const int lane = tid & 31;
    const int wm   = (wid & 3) * (16 * MTILES);
    const int wn   = (wid >> 2) * 64;
    const int g    = lane >> 2;
    const int t    = lane & 3;
    const int m0   = blockIdx.y * AROWS;
    const int n0   = blockIdx.x * 128;

    const int nk = Kp >> 5;

    auto issue = [&](int k0, uint32_t stg) {
        #pragma unroll
        for (int i = 0; i < MTILES; ++i) {
            const int slot = tid + i * 256;
            const int row = slot >> 2, ch = slot & 3;
            const int gm = m0 + row;
            const int ok = gm < M;
            const long off = (long)(ok ? gm : 0) * Kp + ch * 8 + k0;
            const uint32_t d = row * 80 + ch * 16;
            cp16(stg + 0       + d, A0 + off, ok);
            cp16(stg + OFF_A1_ + d, A1 + off, ok);
        }
        #pragma unroll
        for (int i = 0; i < 2; ++i) {
            const int slot = tid + i * 256;
            const int row = slot >> 2, ch = slot & 3;
            const int gn = n0 + row;
            const int ok = gn < N;
            const long off = (long)(ok ? gn : 0) * Kp + ch * 8 + k0;
            const uint32_t d = row * 80 + ch * 16;
            cp16(stg + OFF_B0_ + d, B0 + off, ok);
            cp16(stg + OFF_B1_ + d, B1 + off, ok);
        }
        cp_commit();
    };

    float acc[MTILES][8][4];
    #pragma unroll
    for (int a = 0; a < MTILES; a++)
        #pragma unroll
        for (int b = 0; b < 8; b++)
            #pragma unroll
            for (int c = 0; c < 4; c++) acc[a][b][c] = 0.f;

    issue(0, base);

    for (int it = 0; it < nk; ++it) {
        const int s = it & 1;
        const uint32_t stg_u = base + (uint32_t)s * STG;

        if (it + 1 < nk) {
            issue((it + 1) << 5, base + (uint32_t)(s ^ 1) * STG);
            asm volatile("cp.async.wait_group 1;" ::: "memory");
        } else {
            asm volatile("cp.async.wait_group 0;" ::: "memory");
        }
        __syncthreads();

        #pragma unroll
        for (int ks = 0; ks < 2; ++ks) {
            uint32_t aH[MTILES][4], aL[MTILES][4];
            {
                const int arw = (lane & 15);
                const int kwo = ks * 8 + (lane >> 4) * 4;
                #pragma unroll
                for (int mt = 0; mt < MTILES; ++mt) {
                    const uint32_t ad = stg_u + (wm + mt * 16 + arw) * 80 + kwo * 4;
                    ldm4(aH[mt][0], aH[mt][1], aH[mt][2], aH[mt][3], ad + 0);
                    ldm4(aL[mt][0], aL[mt][1], aL[mt][2], aL[mt][3], ad + OFF_A1_);
                }
            }
            const int brw = (lane >> 4) * 8 + (lane & 7);
            const int bkw = ks * 8 + ((lane >> 3) & 1) * 4;
            #pragma unroll
            for (int p = 0; p < 4; ++p) {
                uint32_t bH[4], bL[4];
                const uint32_t bd = stg_u + (wn + p * 16 + brw) * 80 + bkw * 4;
                ldm4(bH[0], bH[1], bH[2], bH[3], bd + OFF_B0_);
                ldm4(bL[0], bL[1], bL[2], bL[3], bd + OFF_B1_);
                #pragma unroll
                for (int sub = 0; sub < 2; ++sub) {
                    const int nt = 2 * p + sub;
                    uint32_t b_h[2] = {bH[sub * 2], bH[sub * 2 + 1]};
                    uint32_t b_l[2] = {bL[sub * 2], bL[sub * 2 + 1]};
                    #pragma unroll
                    for (int mt = 0; mt < MTILES; ++mt) {
                        mma_f16(acc[mt][nt], aH[mt], b_h);
                        mma_f16(acc[mt][nt], aH[mt], b_l);
                        mma_f16(acc[mt][nt], aL[mt], b_h);
                    }
                }
            }
        }
        __syncthreads();
    }

    // ---- epilogue: stores ----
    const bool neven = ((N & 1) == 0);
    #pragma unroll
    for (int mt = 0; mt < MTILES; ++mt) {
        #pragma unroll
        for (int half = 0; half < 2; ++half) {
            const int gm = m0 + wm + mt * 16 + g + half * 8;
            if (gm >= M) continue;
            const int orow = perm ? ((gm & 1023) * 30 + (gm >> 10)) : gm;
            #pragma unroll
            for (int nt = 0; nt < 8; ++nt) {
                const int col = n0 + wn + nt * 8 + t * 2;
                if (col >= N) continue;
                float v0 = acc[mt][nt][half * 2 + 0];
                float v1 = acc[mt][nt][half * 2 + 1];
                if (bias) {
                    v0 += bias[col];
                    if (col + 1 < N) v1 += bias[col + 1];
                }
                if (Cf) {
                    if (neven && col + 1 < N) {
                        *(float2*)&Cf[(long)orow * N + col] = make_float2(v0, v1);
                    } else {
                        Cf[(long)orow * N + col] = v0;
                        if (col + 1 < N) Cf[(long)orow * N + col + 1] = v1;
                    }
                }
                if (C0 && neven && col + 1 < N) {
                    __half h0, l0, h1, l1;
                    f16split(v0, h0, l0);
                    f16split(v1, h1, l1);
                    *(__half2*)&C0[(long)orow * N + col] = __halves2half2(h0, h1);
                    *(__half2*)&C1[(long)orow * N + col] = __halves2half2(l0, l1);
                }
            }
        }
    }

    // ---- fused BN stats (raw accumulators; bias is null for these layers) ----
    if (gsum) {
        float* ssum = (float*)smg;        // 128 col sums
        float* ssq2 = ssum + 128;         // 128 col sum-sq
        if (tid < 256) ((float*)smg)[tid] = 0.0f;
        __syncthreads();
        #pragma unroll
        for (int nt = 0; nt < 8; ++nt) {
            #pragma unroll
            for (int j = 0; j < 2; ++j) {
                float s = 0.f, s2 = 0.f;
                #pragma unroll
                for (int mt = 0; mt < MTILES; ++mt) {
                    #pragma unroll
                    for (int half = 0; half < 2; ++half) {
                        const float v = acc[mt][nt][half * 2 + j];
                        s += v; s2 += v * v;
                    }
                }
                // reduce the 8 lanes (g=0..7) sharing this column
                #pragma unroll
                for (int o = 16; o >= 4; o >>= 1) {
                    s  += __shfl_down_sync(0xffffffffu, s,  o);
                    s2 += __shfl_down_sync(0xffffffffu, s2, o);
                }
                if (g == 0) {
                    const int cl = wn + nt * 8 + t * 2 + j;
                    atomicAdd(&ssum[cl], s);
                    atomicAdd(&ssq2[cl], s2);
                }
            }
        }
        __syncthreads();
        if (tid < 128 && n0 + tid < N) {
            atomicAdd(&gsum[(n0 + tid) & 511], ssum[tid]);
            atomicAdd(&gssq[(n0 + tid) & 511], ssq2[tid]);
        }
    }
}

constexpr int DS2 = 2 * (2 * 128 * 80 + 2 * 128 * 80) + 1024;   // MTILES=2
constexpr int DS1 = 2 * (2 * 64 * 80 + 2 * 128 * 80) + 1024;    // MTILES=1

// ======================= single prep kernel ================================
// blockIdx.y selects the job; each job grid-strides with gridDim.x*256 threads.
__global__ void prep_all(const float* __restrict__ w_e1, const float* __restrict__ w_e2,
                         const float* __restrict__ w_e3, const float* __restrict__ w_d1,
                         const float* __restrict__ w_d2, const float* __restrict__ w_d3,
                         const float* __restrict__ W_in, const float* __restrict__ W_q,
                         const float* __restrict__ W_out, const float* __restrict__ cb,
                         const float* __restrict__ input,
                         __half* hb, float* cn, float* stats, float* loss, int* cnt)
{
    const int  job = blockIdx.y;
    const long tid0 = (long)blockIdx.x * blockDim.x + threadIdx.x;
    const long strd = (long)gridDim.x * blockDim.x;

    auto enc = [&](const float* w, __half* h0, __half* h1, int Kk, int Kp) {
        const int I = 512, Ke = I * Kk;
        const long n = 512L * Kp;
        for (long j = tid0; j < n; j += strd) {
            const int o  = (int)(j / Kp);
            const int kk = (int)(j % Kp);
            float x = 0.f;
            if (kk < Ke) x = w[(long)o * Ke + (long)(kk % I) * Kk + (kk / I)];
            __half h, l; f16split(x, h, l);
            h0[j] = h; h1[j] = l;
        }
    };
    auto dec = [&](const float* w, __half* h0, __half* h1, int Kk) {
        const int I = 512, O = 512;
        const long n = (long)Kk * O * I;
        for (long j = tid0; j < n; j += strd) {
            const int i  = (int)(j % I);
            const int nn = (int)(j / I);
            const int o  = nn % O;
            const int k  = nn / O;
            const float x = w[(long)i * O * Kk + (long)o * Kk + k];
            __half h, l; f16split(x, h, l);
            h0[j] = h; h1[j] = l;
        }
    };
    auto tr = [&](const float* in, __half* h0, __half* h1, int R, int C, int Kp) {
        const long n = (long)C * Kp;
        for (long j = tid0; j < n; j += strd) {
            const int c = (int)(j / Kp);
            const int r = (int)(j % Kp);
            const float x = (r < R) ? in[(long)r * C + c] : 0.f;
            __half h, l; f16split(x, h, l);
            h0[j] = h; h1[j] = l;
        }
    };

    switch (job) {
    case 0: enc(w_e1, hb + H_WE1, hb + H_WE1 + 512L * 2560, 5, 2560); break;
    case 1: enc(w_e2, hb + H_WE2, hb + H_WE2 + 512L * 1536, 3, 1536); break;
    case 2: enc(w_e3, hb + H_WE3, hb + H_WE3 + 512L * 1024, 2, 1024); break;
    case 3: dec(w_d1, hb + H_WD1, hb + H_WD1 + 1024L * 512, 2); break;
    case 4: dec(w_d2, hb + H_WD2, hb + H_WD2 + 1536L * 512, 3); break;
    case 5: dec(w_d3, hb + H_WD3, hb + H_WD3 + 2560L * 512, 5); break;
    case 6: tr(W_in,  hb + H_WIT, hb + H_WIT + 512L * 160, 135, 512, 160); break;
    case 7: tr(W_q,   hb + H_WQT, hb + H_WQT + 512L * 512, 512, 512, 512); break;
    case 8: tr(W_out, hb + H_WOT, hb + H_WOT + 135L * 512, 512, 135, 512); break;
    case 9: {   // codebook identity split
        __half* h0 = hb + H_CB; __half* h1 = h0 + 512L * 512;
        for (long j = tid0; j < 512L * 512; j += strd) {
            __half h, l; f16split(cb[j], h, l);
            h0[j] = h; h1[j] = l;
        }
        break;
    }
    case 10: {  // input row-pad split [30720,135] -> [30720,160]
        __half* h0 = hb + H_XIN; __half* h1 = h0 + 30720L * 160;
        const long n = 30720L * 160;
        for (long j = tid0; j < n; j += strd) {
            const long r = j / 160;
            const int  c = (int)(j % 160);
            const float x = (c < 135) ? input[r * 135 + c] : 0.f;
            __half h, l; f16split(x, h, l);
            h0[j] = h; h1[j] = l;
        }
        break;
    }
    case 11: {  // zero stats/loss/cnt + codebook norms
        for (long j = tid0; j < 6L * 2 * 512; j += strd) stats[j] = 0.0f;
        for (long j = tid0; j < 512; j += strd) cnt[j] = 0;
        if (tid0 == 0) loss[0] = 0.0f;
        for (long k = tid0; k < 512; k += strd) {
            float s = 0.f;
            for (int d = 0; d < 512; ++d) {
                const float v = cb[k * 512 + d];
                s += v * v;
            }
            cn[k] = s;
        }
        break;
    }
    }
}

// ======================= BN normalize (+ReLU) ===============================
__global__ void bn_norm2(const float* __restrict__ X,
                         const float* __restrict__ gamma, const float* __restrict__ beta,
                         const float* __restrict__ gsum, const float* __restrict__ gssq,
                         int M, __half* __restrict__ h0, __half* __restrict__ h1,
                         float* __restrict__ fout)
{
    const float invM = 1.0f / (float)M;
    const int total = M * 512;
    for (int i = blockIdx.x * blockDim.x + threadIdx.x; i < total;
         i += gridDim.x * blockDim.x) {
        const int c  = i & 511;
        const float mn = gsum[c] * invM;
        const float vr = gssq[c] * invM - mn * mn;
        float v = (X[i] - mn) * rsqrtf(vr + EPSV) * gamma[c] + beta[c];
        v = v > 0.0f ? v : 0.0f;
        __half h, l; f16split(v, h, l);
        h0[i] = h; h1[i] = l;
        if (fout) fout[i] = v;
    }
}

// ======================= vector quantization ================================
__global__ void vq_argmin(const float* __restrict__ scores, const float* __restrict__ cnorm,
                          const float* __restrict__ cb,
                          const __half* __restrict__ cb0, const __half* __restrict__ cb1,
                          const float* __restrict__ z,
                          float* __restrict__ q, __half* __restrict__ qh,
                          __half* __restrict__ ql,
                          int* __restrict__ counts, float* __restrict__ loss)
{
    const int n = blockIdx.x;
    const int k = threadIdx.x;
    const float d = cnorm[k] - 2.0f * scores[(long)n * 512 + k];
    __shared__ float sv[512];
    __shared__ int   si[512];
    sv[k] = d; si[k] = k;
    __syncthreads();
    for (int st = 256; st > 0; st >>= 1) {
        if (k < st) {
            const float ov = sv[k + st];
            const int   oi = si[k + st];
            if (ov < sv[k] || (ov == sv[k] && oi < si[k])) { sv[k] = ov; si[k] = oi; }
        }
        __syncthreads();
    }
    const int best = si[0];
    __syncthreads();

    const float val = cb[(long)best * 512 + k];
    q [(long)n * 512 + k] = val;
    qh[(long)n * 512 + k] = cb0[(long)best * 512 + k];
    ql[(long)n * 512 + k] = cb1[(long)best * 512 + k];

    const float diff = val - z[(long)n * 512 + k];
    sv[k] = diff * diff;
    __syncthreads();
    for (int st = 256; st > 0; st >>= 1) {
        if (k < st) sv[k] += sv[k + st];
        __syncthreads();
    }
    if (k == 0) {
        atomicAdd(&counts[best], 1);
        atomicAdd(loss, sv[0]);
    }
}

__global__ void finalize_k(const int* __restrict__ counts, const float* __restrict__ loss,
                           float* __restrict__ out, long outsize)
{
    const int k = threadIdx.x;
    const float p = (float)counts[k] * (1.0f / 1024.0f);
    __shared__ float sh[512];
    sh[k] = p * logf(p + 1e-10f);
    __syncthreads();
    for (int st = 256; st > 0; st >>= 1) {
        if (k < st) sh[k] += sh[k + st];
        __syncthreads();
    }
    if (k == 0) {
        const long R = 1024L * 30 * 135;
        if (outsize >= R + 2) {
            out[R]     = loss[0] * 1.25f / (1024.0f * 512.0f);
            out[R + 1] = expf(-sh[0]);
        }
    }
}

// ======================= host launch ========================================
static inline dim3 grid128(int M, int N) { return dim3((N + 127) / 128, (M + 127) / 128); }
static inline dim3 grid64(int M, int N)  { return dim3((N + 127) / 128, (M + 63) / 64); }

static void run_bn(const float* X, const float* g, const float* b, int M,
                   float* stats, int layer, __half* h0, __half* h1, float* fout)
{
    float* sum = stats + layer * 1024;
    float* ssq = sum + 512;
    int nb = (M * 512 + 255) / 256; if (nb > 2048) nb = 2048;
    bn_norm2<<<nb, 256>>>(X, g, b, sum, ssq, M, h0, h1, fout);
}

extern "C" void kernel_launch(void* const* d_in, const int* in_sizes, int n_in,
                              void* d_out, int out_size)
{
    (void)in_sizes; (void)n_in;
    float* buf = nullptr;
    __half* hb = nullptr;
    cudaGetSymbolAddress((void**)&buf, g_buf);
    cudaGetSymbolAddress((void**)&hb, g_hbuf);
    cudaFuncSetAttribute(gemm_hh<2>, cudaFuncAttributeMaxDynamicSharedMemorySize, DS2);
    cudaFuncSetAttribute(gemm_hh<1>, cudaFuncAttributeMaxDynamicSharedMemorySize, DS1);

    const float* input = (const float*)d_in[0];
    const float* W_in  = (const float*)d_in[1];
    const float* b_in  = (const float*)d_in[2];
    const float* w_e1  = (const float*)d_in[3];
    const float* g_e1  = (const float*)d_in[4];
    const float* b_e1  = (const float*)d_in[5];
    const float* w_e2  = (const float*)d_in[6];
    const float* g_e2  = (const float*)d_in[7];
    const float* b_e2  = (const float*)d_in[8];
    const float* w_e3  = (const float*)d_in[9];
    const float* g_e3  = (const float*)d_in[10];
    const float* b_e3  = (const float*)d_in[11];
    const float* cb    = (const float*)d_in[12];
    const float* W_q   = (const float*)d_in[13];
    const float* b_q   = (const float*)d_in[14];
    const float* w_d1  = (const float*)d_in[15];
    const float* g_d1  = (const float*)d_in[16];
    const float* b_d1  = (const float*)d_in[17];
    const float* w_d2  = (const float*)d_in[18];
    const float* g_d2  = (const float*)d_in[19];
    const float* b_d2  = (const float*)d_in[20];
    const float* w_d3  = (const float*)d_in[21];
    const float* g_d3  = (const float*)d_in[22];
    const float* b_d3  = (const float*)d_in[23];
    const float* W_out = (const float*)d_in[24];
    const float* b_out = (const float*)d_in[25];

    float* e1r  = buf + O_E1R;
    float* e2r  = buf + O_E2R;
    float* zr   = buf + O_ZR;
    float* z    = buf + O_Z;
    float* q    = buf + O_Q;
    float* d1r  = buf + O_D1R;
    float* d2r  = buf + O_D2R;
    float* d3r  = buf + O_D3R;
    float* sc   = buf + O_SC;
    float* cn   = buf + O_CN;
    float* stats= buf + O_STAT;
    float* loss = buf + O_LOSS;
    int*   cnt  = (int*)(buf + O_CNT);

    __half* we1_0 = hb + H_WE1; __half* we1_1 = we1_0 + 512L * 2560;
    __half* we2_0 = hb + H_WE2; __half* we2_1 = we2_0 + 512L * 1536;
    __half* we3_0 = hb + H_WE3; __half* we3_1 = we3_0 + 512L * 1024;
    __half* wd1_0 = hb + H_WD1; __half* wd1_1 = wd1_0 + 1024L * 512;
    __half* wd2_0 = hb + H_WD2; __half* wd2_1 = wd2_0 + 1536L * 512;
    __half* wd3_0 = hb + H_WD3; __half* wd3_1 = wd3_0 + 2560L * 512;
    __half* wit_0 = hb + H_WIT; __half* wit_1 = wit_0 + 512L * 160;
    __half* wqt_0 = hb + H_WQT; __half* wqt_1 = wqt_0 + 512L * 512;
    __half* wot_0 = hb + H_WOT; __half* wot_1 = wot_0 + 135L * 512;
    __half* cb_0  = hb + H_CB;  __half* cb_1  = cb_0  + 512L * 512;
    __half* xin_0 = hb + H_XIN; __half* xin_1 = xin_0 + 30720L * 160;
    __half* x0_0  = hb + H_X0;  __half* x0_1  = x0_0  + 30720L * 512;
    __half* e1_0  = hb + H_E1;  __half* e1_1  = e1_0  + 6144L * 512;
    __half* e2_0  = hb + H_E2;  __half* e2_1  = e2_0  + 2048L * 512;
    __half* z_0   = hb + H_Z;   __half* z_1   = z_0   + 1024L * 512;
    __half* q_0   = hb + H_Q;   __half* q_1   = q_0   + 1024L * 512;
    __half* d0_0  = hb + H_D0;  __half* d0_1  = d0_0  + 1024L * 512;
    __half* d1_0  = hb + H_D1;  __half* d1_1  = d1_0  + 1024L * 1024;
    __half* d2_0  = hb + H_D2;  __half* d2_1  = d2_0  + 2048L * 1536;
    __half* d3_0  = hb + H_D3;  __half* d3_1  = d3_0  + 30720L * 512;

    float* out = (float*)d_out;

    // ---- prep: everything in ONE launch ----
    prep_all<<<dim3(64, 12), 256>>>(w_e1, w_e2, w_e3, w_d1, w_d2, w_d3,
                                    W_in, W_q, W_out, cb, input,
                                    hb, cn, stats, loss, cnt);

    float* st0 = stats;             // per-layer (sum,ssq) pairs
    float* st1 = stats + 1024;
    float* st2 = stats + 2048;
    float* st3 = stats + 3072;
    float* st4 = stats + 4096;
    float* st5 = stats + 5120;

    // ---- input GEMM: K=135(pad160) -> 512, split-only out, perm ----
    gemm_hh<2><<<grid128(30720, 512), 256, DS2>>>(
        xin_0, xin_1, wit_0, wit_1, b_in, nullptr, x0_0, x0_1,
        nullptr, nullptr, 30720, 512, 160, 1);

    // ---- encoder (stats fused into GEMM epilogues) ----
    gemm_hh<2><<<grid128(6144, 512), 256, DS2>>>(
        x0_0, x0_1, we1_0, we1_1, nullptr, e1r, nullptr, nullptr,
        st0, st0 + 512, 6144, 512, 2560, 0);
    run_bn(e1r, g_e1, b_e1, 6144, stats, 0, e1_0, e1_1, nullptr);

    gemm_hh<1><<<grid64(2048, 512), 256, DS1>>>(
        e1_0, e1_1, we2_0, we2_1, nullptr, e2r, nullptr, nullptr,
        st1, st1 + 512, 2048, 512, 1536, 0);
    run_bn(e2r, g_e2, b_e2, 2048, stats, 1, e2_0, e2_1, nullptr);

    gemm_hh<1><<<grid64(1024, 512), 256, DS1>>>(
        e2_0, e2_1, we3_0, we3_1, nullptr, zr, nullptr, nullptr,
        st2, st2 + 512, 1024, 512, 1024, 0);
    run_bn(zr, g_e3, b_e3, 1024, stats, 2, z_0, z_1, z);

    // ---- vector quantization ----
    gemm_hh<1><<<grid64(1024, 512), 256, DS1>>>(
        z_0, z_1, cb_0, cb_1, nullptr, sc, nullptr, nullptr,
        nullptr, nullptr, 1024, 512, 512, 0);
    vq_argmin<<<1024, 512>>>(sc, cn, cb, cb_0, cb_1, z, q, q_0, q_1, cnt, loss);

    // ---- decoder ----
    gemm_hh<1><<<grid64(1024, 512), 256, DS1>>>(
        q_0, q_1, wqt_0, wqt_1, b_q, nullptr, d0_0, d0_1,
        nullptr, nullptr, 1024, 512, 512, 0);

    gemm_hh<1><<<grid64(1024, 1024), 256, DS1>>>(
        d0_0, d0_1, wd1_0, wd1_1, nullptr, d1r, nullptr, nullptr,
        st3, st3 + 512, 1024, 1024, 512, 0);
    run_bn(d1r, g_d1, b_d1, 2048, stats, 3, d1_0, d1_1, nullptr);

    gemm_hh<2><<<grid128(2048, 1536), 256, DS2>>>(
        d1_0, d1_1, wd2_0, wd2_1, nullptr, d2r, nullptr, nullptr,
        st4, st4 + 512, 2048, 1536, 512, 0);
    run_bn(d2r, g_d2, b_d2, 6144, stats, 4, d2_0, d2_1, nullptr);

    gemm_hh<2><<<grid128(6144, 2560), 256, DS2>>>(
        d2_0, d2_1, wd3_0, wd3_1, nullptr, d3r, nullptr, nullptr,
        st5, st5 + 512, 6144, 2560, 512, 0);
    run_bn(d3r, g_d3, b_d3, 30720, stats, 5, d3_0, d3_1, nullptr);

    // ---- output GEMM -> recon ----
    gemm_hh<2><<<grid128(30720, 135), 256, DS2>>>(
        d3_0, d3_1, wot_0, wot_1, b_out, out, nullptr, nullptr,
        nullptr, nullptr, 30720, 135, 512, 0);

    // ---- scalars ----
    finalize_k<<<1, 512>>>(cnt, loss, out, (long)out_size);
}

// round 10
// speedup vs baseline: 2.6170x; 1.0905x over previous
#include <cuda_runtime.h>
#include <cuda_fp16.h>
#include <math.h>
#include <stdint.h>

// ---------------------------------------------------------------------------
// VQ-VAE forward. T=30, B=1024, D_POSE=135, H=512, K_CODES=512.
// Activations [b, position, channel] -> every conv/convT/linear is a row-major
// GEMM C[M,N] = A[M,K] * B'[N,K]^T on mma.sync.m16n8k16 f16 with 3xFP16
// hi/lo split (err ~2^-24). All operands pre-split f16 in gmem; mainloop is
// pure cp.async + ldmatrix + mma. BN stats fused into GEMM epilogue.
// R10: __launch_bounds__(256,2) on the big-tile GEMM -> 2 CTAs/SM.
// ---------------------------------------------------------------------------

#define EPSV 1e-5f

// ======================= fp32 scratch ======================================
constexpr long O_E1R = 0;                        // 6144 x 512 (raw, pre-BN)
constexpr long O_E2R = O_E1R + 6144L * 512;      // 2048 x 512
constexpr long O_ZR  = O_E2R + 2048L * 512;      // 1024 x 512
constexpr long O_Z   = O_ZR  + 1024L * 512;      // 1024 x 512 (normalized)
constexpr long O_Q   = O_Z   + 1024L * 512;      // 1024 x 512
constexpr long O_D1R = O_Q   + 1024L * 512;      // 1024 x 1024
constexpr long O_D2R = O_D1R + 1024L * 1024;     // 2048 x 1536
constexpr long O_D3R = O_D2R + 2048L * 1536;     // 6144 x 2560
constexpr long O_SC  = O_D3R + 6144L * 2560;     // 1024 x 512
constexpr long O_CN  = O_SC  + 1024L * 512;      // 512
constexpr long O_STAT= O_CN  + 512;              // 6 x 2 x 512
constexpr long O_LOSS= O_STAT+ 6L * 2 * 512;
constexpr long O_CNT = O_LOSS+ 512;
constexpr long TOTALF= O_CNT + 512;

__device__ float g_buf[TOTALF];

// ======================= f16 split scratch (hi then lo per buffer) =========
constexpr long H_WE1 = 0;                          // [512,2560]
constexpr long H_WE2 = H_WE1 + 2L * 512 * 2560;    // [512,1536]
constexpr long H_WE3 = H_WE2 + 2L * 512 * 1536;    // [512,1024]
constexpr long H_WD1 = H_WE3 + 2L * 512 * 1024;    // [1024,512]
constexpr long H_WD2 = H_WD1 + 2L * 1024 * 512;    // [1536,512]
constexpr long H_WD3 = H_WD2 + 2L * 1536 * 512;    // [2560,512]
constexpr long H_WIT = H_WD3 + 2L * 2560 * 512;    // [512,160]
constexpr long H_WQT = H_WIT + 2L * 512 * 160;     // [512,512]
constexpr long H_WOT = H_WQT + 2L * 512 * 512;     // [135,512]
constexpr long H_CB  = H_WOT + 2L * 135 * 512;     // [512,512]
constexpr long H_XIN = H_CB  + 2L * 512 * 512;     // [30720,160]
constexpr long H_X0  = H_XIN + 2L * 30720 * 160;   // [30720,512]
constexpr long H_E1  = H_X0  + 2L * 30720 * 512;   // [6144,512]
constexpr long H_E2  = H_E1  + 2L * 6144 * 512;    // [2048,512]
constexpr long H_Z   = H_E2  + 2L * 2048 * 512;    // [1024,512]
constexpr long H_Q   = H_Z   + 2L * 1024 * 512;    // [1024,512]
constexpr long H_D0  = H_Q   + 2L * 1024 * 512;    // [1024,512]
constexpr long H_D1  = H_D0  + 2L * 1024 * 512;    // [1024,1024]
constexpr long H_D2  = H_D1  + 2L * 1024 * 1024;   // [2048,1536]
constexpr long H_D3  = H_D2  + 2L * 2048 * 1536;   // [30720,512]
constexpr long TOTALH= H_D3  + 2L * 30720 * 512;

__device__ __half g_hbuf[TOTALH];

// ======================= helpers ===========================================
__device__ __forceinline__ uint32_t smem_u32(const void* p)
{
    return (uint32_t)__cvta_generic_to_shared(p);
}

__device__ __forceinline__ void f16split(float x, __half& h, __half& l)
{
    h = __float2half_rn(x);
    l = __float2half_rn(x - __half2float(h));
}

__device__ __forceinline__ void mma_f16(float* c, const uint32_t* a, const uint32_t* b)
{
    asm volatile(
        "mma.sync.aligned.m16n8k16.row.col.f32.f16.f16.f32 "
        "{%0,%1,%2,%3}, {%4,%5,%6,%7}, {%8,%9}, {%0,%1,%2,%3};"
        : "+f"(c[0]), "+f"(c[1]), "+f"(c[2]), "+f"(c[3])
        : "r"(a[0]), "r"(a[1]), "r"(a[2]), "r"(a[3]), "r"(b[0]), "r"(b[1]));
}

__device__ __forceinline__ void ldm4(uint32_t& r0, uint32_t& r1, uint32_t& r2,
                                     uint32_t& r3, uint32_t addr)
{
    asm volatile("ldmatrix.sync.aligned.m8n8.x4.shared.b16 {%0,%1,%2,%3}, [%4];"
                 : "=r"(r0), "=r"(r1), "=r"(r2), "=r"(r3) : "r"(addr));
}

__device__ __forceinline__ void cp16(uint32_t dst, const void* src, int pred)
{
    asm volatile("cp.async.cg.shared.global [%0], [%1], 16, %2;"
                 :: "r"(dst), "l"(src), "r"(pred ? 16 : 0) : "memory");
}
__device__ __forceinline__ void cp_commit()
{
    asm volatile("cp.async.commit_group;" ::: "memory");
}

// ======================= GEMM ==============================================
// Templated CTA tile: (64*MTILES) x 128, BK=32 halves, 256 threads, 8 warps
// (4 M x 2 N), warp tile (16*MTILES) x 64. SMEM row stride 80B.
// MTILES=2 is register-capped (launch_bounds 256,2) so two CTAs co-reside
// per SM: cross-CTA overlap hides syncthreads + ldmatrix/mma latency.

template<int MTILES>
__global__
#if 1
__launch_bounds__(256, (MTILES == 2) ? 2 : 1)
#endif
void gemm_hh(const __half* __restrict__ A0, const __half* __restrict__ A1,
             const __half* __restrict__ B0, const __half* __restrict__ B1,
             const float* __restrict__ bias, float* __restrict__ Cf,
             __half* __restrict__ C0, __half* __restrict__ C1,
             float* __restrict__ gsum, float* __restrict__ gssq,
             int M, int N, int Kp, int perm)
{
    constexpr int AROWS  = 64 * MTILES;
    constexpr int OFF_A1_ = AROWS * 80;
    constexpr int OFF_B0_ = 2 * AROWS * 80;
    constexpr int OFF_B1_ = OFF_B0_ + 128 * 80;
    constexpr int STG     = OFF_B0_ + 2 * 128 * 80;

    extern __shared__ char dsm[];
    const uint32_t dynb = smem_u32(dsm);
    const uint32_t base = (dynb + 1023u) & ~1023u;
    char* smg = dsm + (base - dynb);

    const int tid  = threadIdx.x;
    const int wid  = tid >> 5;
    const int lane = tid & 31;
    const int wm   = (wid & 3) * (16 * MTILES);
    const int wn   = (wid >> 2) * 64;
    const int g    = lane >> 2;
    const int t    = lane & 3;
    const int m0   = blockIdx.y * AROWS;
    const int n0   = blockIdx.x * 128;

    const int nk = Kp >> 5;

    auto issue = [&](int k0, uint32_t stg) {
        #pragma unroll
        for (int i = 0; i < MTILES; ++i) {
            const int slot = tid + i * 256;
            const int row = slot >> 2, ch = slot & 3;
            const int gm = m0 + row;
            const int ok = gm < M;
            const long off = (long)(ok ? gm : 0) * Kp + ch * 8 + k0;
            const uint32_t d = row * 80 + ch * 16;
            cp16(stg + 0       + d, A0 + off, ok);
            cp16(stg + OFF_A1_ + d, A1 + off, ok);
        }
        #pragma unroll
        for (int i = 0; i < 2; ++i) {
            const int slot = tid + i * 256;
            const int row = slot >> 2, ch = slot & 3;
            const int gn = n0 + row;
            const int ok = gn < N;
            const long off = (long)(ok ? gn : 0) * Kp + ch * 8 + k0;
            const uint32_t d = row * 80 + ch * 16;
            cp16(stg + OFF_B0_ + d, B0 + off, ok);
            cp16(stg + OFF_B1_ + d, B1 + off, ok);
        }
        cp_commit();
    };

    float acc[MTILES][8][4];
    #pragma unroll
    for (int a = 0; a < MTILES; a++)
        #pragma unroll
        for (int b = 0; b < 8; b++)
            #pragma unroll
            for (int c = 0; c < 4; c++) acc[a][b][c] = 0.f;

    issue(0, base);

    for (int it = 0; it < nk; ++it) {
        const int s = it & 1;
        const uint32_t stg_u = base + (uint32_t)s * STG;

        if (it + 1 < nk) {
            issue((it + 1) << 5, base + (uint32_t)(s ^ 1) * STG);
            asm volatile("cp.async.wait_group 1;" ::: "memory");
        } else {
            asm volatile("cp.async.wait_group 0;" ::: "memory");
        }
        __syncthreads();

        #pragma unroll
        for (int ks = 0; ks < 2; ++ks) {
            uint32_t aH[MTILES][4], aL[MTILES][4];
            {
                const int arw = (lane & 15);
                const int kwo = ks * 8 + (lane >> 4) * 4;
                #pragma unroll
                for (int mt = 0; mt < MTILES; ++mt) {
                    const uint32_t ad = stg_u + (wm + mt * 16 + arw) * 80 + kwo * 4;
                    ldm4(aH[mt][0], aH[mt][1], aH[mt][2], aH[mt][3], ad + 0);
                    ldm4(aL[mt][0], aL[mt][1], aL[mt][2], aL[mt][3], ad + OFF_A1_);
                }
            }
            const int brw = (lane >> 4) * 8 + (lane & 7);
            const int bkw = ks * 8 + ((lane >> 3) & 1) * 4;
            #pragma unroll
            for (int p = 0; p < 4; ++p) {
                uint32_t bH[4], bL[4];
                const uint32_t bd = stg_u + (wn + p * 16 + brw) * 80 + bkw * 4;
                ldm4(bH[0], bH[1], bH[2], bH[3], bd + OFF_B0_);
                ldm4(bL[0], bL[1], bL[2], bL[3], bd + OFF_B1_);
                #pragma unroll
                for (int sub = 0; sub < 2; ++sub) {
                    const int nt = 2 * p + sub;
                    uint32_t b_h[2] = {bH[sub * 2], bH[sub * 2 + 1]};
                    uint32_t b_l[2] = {bL[sub * 2], bL[sub * 2 + 1]};
                    #pragma unroll
                    for (int mt = 0; mt < MTILES; ++mt) {
                        mma_f16(acc[mt][nt], aH[mt], b_h);
                        mma_f16(acc[mt][nt], aH[mt], b_l);
                        mma_f16(acc[mt][nt], aL[mt], b_h);
                    }
                }
            }
        }
        __syncthreads();
    }

    // ---- epilogue: stores ----
    const bool neven = ((N & 1) == 0);
    #pragma unroll
    for (int mt = 0; mt < MTILES; ++mt) {
        #pragma unroll
        for (int half = 0; half < 2; ++half) {
            const int gm = m0 + wm + mt * 16 + g + half * 8;
            if (gm >= M) continue;
            const int orow = perm ? ((gm & 1023) * 30 + (gm >> 10)) : gm;
            #pragma unroll
            for (int nt = 0; nt < 8; ++nt) {
                const int col = n0 + wn + nt * 8 + t * 2;
                if (col >= N) continue;
                float v0 = acc[mt][nt][half * 2 + 0];
                float v1 = acc[mt][nt][half * 2 + 1];
                if (bias) {
                    v0 += bias[col];
                    if (col + 1 < N) v1 += bias[col + 1];
                }
                if (Cf) {
                    if (neven && col + 1 < N) {
                        *(float2*)&Cf[(long)orow * N + col] = make_float2(v0, v1);
                    } else {
                        Cf[(long)orow * N + col] = v0;
                        if (col + 1 < N) Cf[(long)orow * N + col + 1] = v1;
                    }
                }
                if (C0 && neven && col + 1 < N) {
                    __half h0, l0, h1, l1;
                    f16split(v0, h0, l0);
                    f16split(v1, h1, l1);
                    *(__half2*)&C0[(long)orow * N + col] = __halves2half2(h0, h1);
                    *(__half2*)&C1[(long)orow * N + col] = __halves2half2(l0, l1);
                }
            }
        }
    }

    // ---- fused BN stats (raw accumulators; bias null for these layers) ----
    if (gsum) {
        float* ssum = (float*)smg;        // 128 col sums
        float* ssq2 = ssum + 128;         // 128 col sum-sq
        if (tid < 256) ((float*)smg)[tid] = 0.0f;
        __syncthreads();
        #pragma unroll
        for (int nt = 0; nt < 8; ++nt) {
            #pragma unroll
            for (int j = 0; j < 2; ++j) {
                float s = 0.f, s2 = 0.f;
                #pragma unroll
                for (int mt = 0; mt < MTILES; ++mt) {
                    #pragma unroll
                    for (int half = 0; half < 2; ++half) {
                        const float v = acc[mt][nt][half * 2 + j];
                        s += v; s2 += v * v;
                    }
                }
                #pragma unroll
                for (int o = 16; o >= 4; o >>= 1) {
                    s  += __shfl_down_sync(0xffffffffu, s,  o);
                    s2 += __shfl_down_sync(0xffffffffu, s2, o);
                }
                if (g == 0) {
                    const int cl = wn + nt * 8 + t * 2 + j;
                    atomicAdd(&ssum[cl], s);
                    atomicAdd(&ssq2[cl], s2);
                }
            }
        }
        __syncthreads();
        if (tid < 128 && n0 + tid < N) {
            atomicAdd(&gsum[(n0 + tid) & 511], ssum[tid]);
            atomicAdd(&gssq[(n0 + tid) & 511], ssq2[tid]);
        }
    }
}

constexpr int DS2 = 2 * (2 * 128 * 80 + 2 * 128 * 80) + 1024;   // MTILES=2
constexpr int DS1 = 2 * (2 * 64 * 80 + 2 * 128 * 80) + 1024;    // MTILES=1

// ======================= single prep kernel ================================
__global__ void prep_all(const float* __restrict__ w_e1, const float* __restrict__ w_e2,
                         const float* __restrict__ w_e3, const float* __restrict__ w_d1,
                         const float* __restrict__ w_d2, const float* __restrict__ w_d3,
                         const float* __restrict__ W_in, const float* __restrict__ W_q,
                         const float* __restrict__ W_out, const float* __restrict__ cb,
                         const float* __restrict__ input,
                         __half* hb, float* cn, float* stats, float* loss, int* cnt)
{
    const int  job = blockIdx.y;
    const long tid0 = (long)blockIdx.x * blockDim.x + threadIdx.x;
    const long strd = (long)gridDim.x * blockDim.x;

    auto enc = [&](const float* w, __half* h0, __half* h1, int Kk, int Kp) {
        const int I = 512, Ke = I * Kk;
        const long n = 512L * Kp;
        for (long j = tid0; j < n; j += strd) {
            const int o  = (int)(j / Kp);
            const int kk = (int)(j % Kp);
            float x = 0.f;
            if (kk < Ke) x = w[(long)o * Ke + (long)(kk % I) * Kk + (kk / I)];
            __half h, l; f16split(x, h, l);
            h0[j] = h; h1[j] = l;
        }
    };
    auto dec = [&](const float* w, __half* h0, __half* h1, int Kk) {
        const int I = 512, O = 512;
        const long n = (long)Kk * O * I;
        for (long j = tid0; j < n; j += strd) {
            const int i  = (int)(j % I);
            const int nn = (int)(j / I);
            const int o  = nn % O;
            const int k  = nn / O;
            const float x = w[(long)i * O * Kk + (long)o * Kk + k];
            __half h, l; f16split(x, h, l);
            h0[j] = h; h1[j] = l;
        }
    };
    auto tr = [&](const float* in, __half* h0, __half* h1, int R, int C, int Kp) {
        const long n = (long)C * Kp;
        for (long j = tid0; j < n; j += strd) {
            const int c = (int)(j / Kp);
            const int r = (int)(j % Kp);
            const float x = (r < R) ? in[(long)r * C + c] : 0.f;
            __half h, l; f16split(x, h, l);
            h0[j] = h; h1[j] = l;
        }
    };

    switch (job) {
    case 0: enc(w_e1, hb + H_WE1, hb + H_WE1 + 512L * 2560, 5, 2560); break;
    case 1: enc(w_e2, hb + H_WE2, hb + H_WE2 + 512L * 1536, 3, 1536); break;
    case 2: enc(w_e3, hb + H_WE3, hb + H_WE3 + 512L * 1024, 2, 1024); break;
    case 3: dec(w_d1, hb + H_WD1, hb + H_WD1 + 1024L * 512, 2); break;
    case 4: dec(w_d2, hb + H_WD2, hb + H_WD2 + 1536L * 512, 3); break;
    case 5: dec(w_d3, hb + H_WD3, hb + H_WD3 + 2560L * 512, 5); break;
    case 6: tr(W_in,  hb + H_WIT, hb + H_WIT + 512L * 160, 135, 512, 160); break;
    case 7: tr(W_q,   hb + H_WQT, hb + H_WQT + 512L * 512, 512, 512, 512); break;
    case 8: tr(W_out, hb + H_WOT, hb + H_WOT + 135L * 512, 512, 135, 512); break;
    case 9: {
        __half* h0 = hb + H_CB; __half* h1 = h0 + 512L * 512;
        for (long j = tid0; j < 512L * 512; j += strd) {
            __half h, l; f16split(cb[j], h, l);
            h0[j] = h; h1[j] = l;
        }
        break;
    }
    case 10: {
        __half* h0 = hb + H_XIN; __half* h1 = h0 + 30720L * 160;
        const long n = 30720L * 160;
        for (long j = tid0; j < n; j += strd) {
            const long r = j / 160;
            const int  c = (int)(j % 160);
            const float x = (c < 135) ? input[r * 135 + c] : 0.f;
            __half h, l; f16split(x, h, l);
            h0[j] = h; h1[j] = l;
        }
        break;
    }
    case 11: {
        for (long j = tid0; j < 6L * 2 * 512; j += strd) stats[j] = 0.0f;
        for (long j = tid0; j < 512; j += strd) cnt[j] = 0;
        if (tid0 == 0) loss[0] = 0.0f;
        for (long k = tid0; k < 512; k += strd) {
            float s = 0.f;
            for (int d = 0; d < 512; ++d) {
                const float v = cb[k * 512 + d];
                s += v * v;
            }
            cn[k] = s;
        }
        break;
    }
    }
}

// ======================= BN normalize (+ReLU), 4-wide =======================
__global__ void bn_norm2(const float* __restrict__ X,
                         const float* __restrict__ gamma, const float* __restrict__ beta,
                         const float* __restrict__ gsum, const float* __restrict__ gssq,
                         int M, __half* __restrict__ h0, __half* __restrict__ h1,
                         float* __restrict__ fout)
{
    const float invM = 1.0f / (float)M;
    const int total4 = (M * 512) >> 2;
    for (int i4 = blockIdx.x * blockDim.x + threadIdx.x; i4 < total4;
         i4 += gridDim.x * blockDim.x) {
        const long i = (long)i4 << 2;
        const int c0 = (int)(i & 511);
        const float4 x = *(const float4*)&X[i];
        float v[4] = {x.x, x.y, x.z, x.w};
        __half hh[4], ll[4];
        #pragma unroll
        for (int j = 0; j < 4; ++j) {
            const int c = c0 + j;
            const float mn = gsum[c] * invM;
            const float vr = gssq[c] * invM - mn * mn;
            float y = (v[j] - mn) * rsqrtf(vr + EPSV) * gamma[c] + beta[c];
            y = y > 0.0f ? y : 0.0f;
            v[j] = y;
            f16split(y, hh[j], ll[j]);
        }
        *(__half2*)&h0[i]     = __halves2half2(hh[0], hh[1]);
        *(__half2*)&h0[i + 2] = __halves2half2(hh[2], hh[3]);
        *(__half2*)&h1[i]     = __halves2half2(ll[0], ll[1]);
        *(__half2*)&h1[i + 2] = __halves2half2(ll[2], ll[3]);
        if (fout) *(float4*)&fout[i] = make_float4(v[0], v[1], v[2], v[3]);
    }
}

// ======================= vector quantization ================================
__global__ void vq_argmin(const float* __restrict__ scores, const float* __restrict__ cnorm,
                          const float* __restrict__ cb,
                          const __half* __restrict__ cb0, const __half* __restrict__ cb1,
                          const float* __restrict__ z,
                          float* __restrict__ q, __half* __restrict__ qh,
                          __half* __restrict__ ql,
                          int* __restrict__ counts, float* __restrict__ loss)
{
    const int n = blockIdx.x;
    const int k = threadIdx.x;
    const float d = cnorm[k] - 2.0f * scores[(long)n * 512 + k];
    __shared__ float sv[512];
    __shared__ int   si[512];
    sv[k] = d; si[k] = k;
    __syncthreads();
    for (int st = 256; st > 0; st >>= 1) {
        if (k < st) {
            const float ov = sv[k + st];
            const int   oi = si[k + st];
            if (ov < sv[k] || (ov == sv[k] && oi < si[k])) { sv[k] = ov; si[k] = oi; }
        }
        __syncthreads();
    }
    const int best = si[0];
    __syncthreads();

    const float val = cb[(long)best * 512 + k];
    q [(long)n * 512 + k] = val;
    qh[(long)n * 512 + k] = cb0[(long)best * 512 + k];
    ql[(long)n * 512 + k] = cb1[(long)best * 512 + k];

    const float diff = val - z[(long)n * 512 + k];
    sv[k] = diff * diff;
    __syncthreads();
    for (int st = 256; st > 0; st >>= 1) {
        if (k < st) sv[k] += sv[k + st];
        __syncthreads();
    }
    if (k == 0) {
        atomicAdd(&counts[best], 1);
        atomicAdd(loss, sv[0]);
    }
}

__global__ void finalize_k(const int* __restrict__ counts, const float* __restrict__ loss,
                           float* __restrict__ out, long outsize)
{
    const int k = threadIdx.x;
    const float p = (float)counts[k] * (1.0f / 1024.0f);
    __shared__ float sh[512];
    sh[k] = p * logf(p + 1e-10f);
    __syncthreads();
    for (int st = 256; st > 0; st >>= 1) {
        if (k < st) sh[k] += sh[k + st];
        __syncthreads();
    }
    if (k == 0) {
        const long R = 1024L * 30 * 135;
        if (outsize >= R + 2) {
            out[R]     = loss[0] * 1.25f / (1024.0f * 512.0f);
            out[R + 1] = expf(-sh[0]);
        }
    }
}

// ======================= host launch ========================================
static inline dim3 grid128(int M, int N) { return dim3((N + 127) / 128, (M + 127) / 128); }
static inline dim3 grid64(int M, int N)  { return dim3((N + 127) / 128, (M + 63) / 64); }

static void run_bn(const float* X, const float* g, const float* b, int M,
                   float* stats, int layer, __half* h0, __half* h1, float* fout)
{
    float* sum = stats + layer * 1024;
    float* ssq = sum + 512;
    int nb = (M * 512 / 4 + 255) / 256; if (nb > 2048) nb = 2048;
    bn_norm2<<<nb, 256>>>(X, g, b, sum, ssq, M, h0, h1, fout);
}

extern "C" void kernel_launch(void* const* d_in, const int* in_sizes, int n_in,
                              void* d_out, int out_size)
{
    (void)in_sizes; (void)n_in;
    float* buf = nullptr;
    __half* hb = nullptr;
    cudaGetSymbolAddress((void**)&buf, g_buf);
    cudaGetSymbolAddress((void**)&hb, g_hbuf);
    cudaFuncSetAttribute(gemm_hh<2>, cudaFuncAttributeMaxDynamicSharedMemorySize, DS2);
    cudaFuncSetAttribute(gemm_hh<1>, cudaFuncAttributeMaxDynamicSharedMemorySize, DS1);

    const float* input = (const float*)d_in[0];
    const float* W_in  = (const float*)d_in[1];
    const float* b_in  = (const float*)d_in[2];
    const float* w_e1  = (const float*)d_in[3];
    const float* g_e1  = (const float*)d_in[4];
    const float* b_e1  = (const float*)d_in[5];
    const float* w_e2  = (const float*)d_in[6];
    const float* g_e2  = (const float*)d_in[7];
    const float* b_e2  = (const float*)d_in[8];
    const float* w_e3  = (const float*)d_in[9];
    const float* g_e3  = (const float*)d_in[10];
    const float* b_e3  = (const float*)d_in[11];
    const float* cb    = (const float*)d_in[12];
    const float* W_q   = (const float*)d_in[13];
    const float* b_q   = (const float*)d_in[14];
    const float* w_d1  = (const float*)d_in[15];
    const float* g_d1  = (const float*)d_in[16];
    const float* b_d1  = (const float*)d_in[17];
    const float* w_d2  = (const float*)d_in[18];
    const float* g_d2  = (const float*)d_in[19];
    const float* b_d2  = (const float*)d_in[20];
    const float* w_d3  = (const float*)d_in[21];
    const float* g_d3  = (const float*)d_in[22];
    const float* b_d3  = (const float*)d_in[23];
    const float* W_out = (const float*)d_in[24];
    const float* b_out = (const float*)d_in[25];

    float* e1r  = buf + O_E1R;
    float* e2r  = buf + O_E2R;
    float* zr   = buf + O_ZR;
    float* z    = buf + O_Z;
    float* q    = buf + O_Q;
    float* d1r  = buf + O_D1R;
    float* d2r  = buf + O_D2R;
    float* d3r  = buf + O_D3R;
    float* sc   = buf + O_SC;
    float* cn   = buf + O_CN;
    float* stats= buf + O_STAT;
    float* loss = buf + O_LOSS;
    int*   cnt  = (int*)(buf + O_CNT);

    __half* we1_0 = hb + H_WE1; __half* we1_1 = we1_0 + 512L * 2560;
    __half* we2_0 = hb + H_WE2; __half* we2_1 = we2_0 + 512L * 1536;
    __half* we3_0 = hb + H_WE3; __half* we3_1 = we3_0 + 512L * 1024;
    __half* wd1_0 = hb + H_WD1; __half* wd1_1 = wd1_0 + 1024L * 512;
    __half* wd2_0 = hb + H_WD2; __half* wd2_1 = wd2_0 + 1536L * 512;
    __half* wd3_0 = hb + H_WD3; __half* wd3_1 = wd3_0 + 2560L * 512;
    __half* wit_0 = hb + H_WIT; __half* wit_1 = wit_0 + 512L * 160;
    __half* wqt_0 = hb + H_WQT; __half* wqt_1 = wqt_0 + 512L * 512;
    __half* wot_0 = hb + H_WOT; __half* wot_1 = wot_0 + 135L * 512;
    __half* cb_0  = hb + H_CB;  __half* cb_1  = cb_0  + 512L * 512;
    __half* xin_0 = hb + H_XIN; __half* xin_1 = xin_0 + 30720L * 160;
    __half* x0_0  = hb + H_X0;  __half* x0_1  = x0_0  + 30720L * 512;
    __half* e1_0  = hb + H_E1;  __half* e1_1  = e1_0  + 6144L * 512;
    __half* e2_0  = hb + H_E2;  __half* e2_1  = e2_0  + 2048L * 512;
    __half* z_0   = hb + H_Z;   __half* z_1   = z_0   + 1024L * 512;
    __half* q_0   = hb + H_Q;   __half* q_1   = q_0   + 1024L * 512;
    __half* d0_0  = hb + H_D0;  __half* d0_1  = d0_0  + 1024L * 512;
    __half* d1_0  = hb + H_D1;  __half* d1_1  = d1_0  + 1024L * 1024;
    __half* d2_0  = hb + H_D2;  __half* d2_1  = d2_0  + 2048L * 1536;
    __half* d3_0  = hb + H_D3;  __half* d3_1  = d3_0  + 30720L * 512;

    float* out = (float*)d_out;

    // ---- prep: everything in ONE launch ----
    prep_all<<<dim3(160, 12), 256>>>(w_e1, w_e2, w_e3, w_d1, w_d2, w_d3,
                                     W_in, W_q, W_out, cb, input,
                                     hb, cn, stats, loss, cnt);

    float* st0 = stats;
    float* st1 = stats + 1024;
    float* st2 = stats + 2048;
    float* st3 = stats + 3072;
    float* st4 = stats + 4096;
    float* st5 = stats + 5120;

    // ---- input GEMM: K=135(pad160) -> 512, split-only out, perm ----
    gemm_hh<2><<<grid128(30720, 512), 256, DS2>>>(
        xin_0, xin_1, wit_0, wit_1, b_in, nullptr, x0_0, x0_1,
        nullptr, nullptr, 30720, 512, 160, 1);

    // ---- encoder (stats fused into GEMM epilogues) ----
    gemm_hh<2><<<grid128(6144, 512), 256, DS2>>>(
        x0_0, x0_1, we1_0, we1_1, nullptr, e1r, nullptr, nullptr,
        st0, st0 + 512, 6144, 512, 2560, 0);
    run_bn(e1r, g_e1, b_e1, 6144, stats, 0, e1_0, e1_1, nullptr);

    gemm_hh<1><<<grid64(2048, 512), 256, DS1>>>(
        e1_0, e1_1, we2_0, we2_1, nullptr, e2r, nullptr, nullptr,
        st1, st1 + 512, 2048, 512, 1536, 0);
    run_bn(e2r, g_e2, b_e2, 2048, stats, 1, e2_0, e2_1, nullptr);

    gemm_hh<1><<<grid64(1024, 512), 256, DS1>>>(
        e2_0, e2_1, we3_0, we3_1, nullptr, zr, nullptr, nullptr,
        st2, st2 + 512, 1024, 512, 1024, 0);
    run_bn(zr, g_e3, b_e3, 1024, stats, 2, z_0, z_1, z);

    // ---- vector quantization ----
    gemm_hh<1><<<grid64(1024, 512), 256, DS1>>>(
        z_0, z_1, cb_0, cb_1, nullptr, sc, nullptr, nullptr,
        nullptr, nullptr, 1024, 512, 512, 0);
    vq_argmin<<<1024, 512>>>(sc, cn, cb, cb_0, cb_1, z, q, q_0, q_1, cnt, loss);

    // ---- decoder ----
    gemm_hh<1><<<grid64(1024, 512), 256, DS1>>>(
        q_0, q_1, wqt_0, wqt_1, b_q, nullptr, d0_0, d0_1,
        nullptr, nullptr, 1024, 512, 512, 0);

    gemm_hh<1><<<grid64(1024, 1024), 256, DS1>>>(
        d0_0, d0_1, wd1_0, wd1_1, nullptr, d1r, nullptr, nullptr,
        st3, st3 + 512, 1024, 1024, 512, 0);
    run_bn(d1r, g_d1, b_d1, 2048, stats, 3, d1_0, d1_1, nullptr);

    gemm_hh<2><<<grid128(2048, 1536), 256, DS2>>>(
        d1_0, d1_1, wd2_0, wd2_1, nullptr, d2r, nullptr, nullptr,
        st4, st4 + 512, 2048, 1536, 512, 0);
    run_bn(d2r, g_d2, b_d2, 6144, stats, 4, d2_0, d2_1, nullptr);

    gemm_hh<2><<<grid128(6144, 2560), 256, DS2>>>(
        d2_0, d2_1, wd3_0, wd3_1, nullptr, d3r, nullptr, nullptr,
        st5, st5 + 512, 6144, 2560, 512, 0);
    run_bn(d3r, g_d3, b_d3, 30720, stats, 5, d3_0, d3_1, nullptr);

    // ---- output GEMM -> recon ----
    gemm_hh<2><<<grid128(30720, 135), 256, DS2>>>(
        d3_0, d3_1, wot_0, wot_1, b_out, out, nullptr, nullptr,
        nullptr, nullptr, 30720, 135, 512, 0);

    // ---- scalars ----
    finalize_k<<<1, 512>>>(cnt, loss, out, (long)out_size);
}

// round 11
// speedup vs baseline: 3.0583x; 1.1686x over previous
#include <cuda_runtime.h>
#include <cuda_fp16.h>
#include <math.h>
#include <stdint.h>

// ---------------------------------------------------------------------------
// VQ-VAE forward. T=30, B=1024, D_POSE=135, H=512, K_CODES=512.
// Activations [b, position, channel] -> every conv/convT/linear is a row-major
// GEMM C[M,N] = A[M,K] * B'[N,K]^T on mma.sync.m16n8k16 f16 with 3xFP16
// hi/lo split (err ~2^-24). All operands pre-split f16 in gmem; mainloop is
// pure cp.async + ldmatrix + mma. BN stats fused into GEMM epilogue.
// R11: 3-stage cp.async pipeline + 64B swizzled smem rows (2 CTAs/SM kept).
// ---------------------------------------------------------------------------

#define EPSV 1e-5f

// ======================= fp32 scratch ======================================
constexpr long O_E1R = 0;                        // 6144 x 512 (raw, pre-BN)
constexpr long O_E2R = O_E1R + 6144L * 512;      // 2048 x 512
constexpr long O_ZR  = O_E2R + 2048L * 512;      // 1024 x 512
constexpr long O_Z   = O_ZR  + 1024L * 512;      // 1024 x 512 (normalized)
constexpr long O_Q   = O_Z   + 1024L * 512;      // 1024 x 512
constexpr long O_D1R = O_Q   + 1024L * 512;      // 1024 x 1024
constexpr long O_D2R = O_D1R + 1024L * 1024;     // 2048 x 1536
constexpr long O_D3R = O_D2R + 2048L * 1536;     // 6144 x 2560
constexpr long O_SC  = O_D3R + 6144L * 2560;     // 1024 x 512
constexpr long O_CN  = O_SC  + 1024L * 512;      // 512
constexpr long O_STAT= O_CN  + 512;              // 6 x 2 x 512
constexpr long O_LOSS= O_STAT+ 6L * 2 * 512;
constexpr long O_CNT = O_LOSS+ 512;
constexpr long TOTALF= O_CNT + 512;

__device__ float g_buf[TOTALF];

// ======================= f16 split scratch (hi then lo per buffer) =========
constexpr long H_WE1 = 0;                          // [512,2560]
constexpr long H_WE2 = H_WE1 + 2L * 512 * 2560;    // [512,1536]
constexpr long H_WE3 = H_WE2 + 2L * 512 * 1536;    // [512,1024]
constexpr long H_WD1 = H_WE3 + 2L * 512 * 1024;    // [1024,512]
constexpr long H_WD2 = H_WD1 + 2L * 1024 * 512;    // [1536,512]
constexpr long H_WD3 = H_WD2 + 2L * 1536 * 512;    // [2560,512]
constexpr long H_WIT = H_WD3 + 2L * 2560 * 512;    // [512,160]
constexpr long H_WQT = H_WIT + 2L * 512 * 160;     // [512,512]
constexpr long H_WOT = H_WQT + 2L * 512 * 512;     // [135,512]
constexpr long H_CB  = H_WOT + 2L * 135 * 512;     // [512,512]
constexpr long H_XIN = H_CB  + 2L * 512 * 512;     // [30720,160]
constexpr long H_X0  = H_XIN + 2L * 30720 * 160;   // [30720,512]
constexpr long H_E1  = H_X0  + 2L * 30720 * 512;   // [6144,512]
constexpr long H_E2  = H_E1  + 2L * 6144 * 512;    // [2048,512]
constexpr long H_Z   = H_E2  + 2L * 2048 * 512;    // [1024,512]
constexpr long H_Q   = H_Z   + 2L * 1024 * 512;    // [1024,512]
constexpr long H_D0  = H_Q   + 2L * 1024 * 512;    // [1024,512]
constexpr long H_D1  = H_D0  + 2L * 1024 * 512;    // [1024,1024]
constexpr long H_D2  = H_D1  + 2L * 1024 * 1024;   // [2048,1536]
constexpr long H_D3  = H_D2  + 2L * 2048 * 1536;   // [30720,512]
constexpr long TOTALH= H_D3  + 2L * 30720 * 512;

__device__ __half g_hbuf[TOTALH];

// ======================= helpers ===========================================
__device__ __forceinline__ uint32_t smem_u32(const void* p)
{
    return (uint32_t)__cvta_generic_to_shared(p);
}

__device__ __forceinline__ void f16split(float x, __half& h, __half& l)
{
    h = __float2half_rn(x);
    l = __float2half_rn(x - __half2float(h));
}

__device__ __forceinline__ void mma_f16(float* c, const uint32_t* a, const uint32_t* b)
{
    asm volatile(
        "mma.sync.aligned.m16n8k16.row.col.f32.f16.f16.f32 "
        "{%0,%1,%2,%3}, {%4,%5,%6,%7}, {%8,%9}, {%0,%1,%2,%3};"
        : "+f"(c[0]), "+f"(c[1]), "+f"(c[2]), "+f"(c[3])
        : "r"(a[0]), "r"(a[1]), "r"(a[2]), "r"(a[3]), "r"(b[0]), "r"(b[1]));
}

__device__ __forceinline__ void ldm4(uint32_t& r0, uint32_t& r1, uint32_t& r2,
                                     uint32_t& r3, uint32_t addr)
{
    asm volatile("ldmatrix.sync.aligned.m8n8.x4.shared.b16 {%0,%1,%2,%3}, [%4];"
                 : "=r"(r0), "=r"(r1), "=r"(r2), "=r"(r3) : "r"(addr));
}

__device__ __forceinline__ void cp16(uint32_t dst, const void* src, int pred)
{
    asm volatile("cp.async.cg.shared.global [%0], [%1], 16, %2;"
                 :: "r"(dst), "l"(src), "r"(pred ? 16 : 0) : "memory");
}
__device__ __forceinline__ void cp_commit()
{
    asm volatile("cp.async.commit_group;" ::: "memory");
}

// 64B rows, chunk swizzle: byte = row*64 + ((ch ^ ((row>>1)&3)) * 16)
__device__ __forceinline__ uint32_t swz(int row, int ch)
{
    return (uint32_t)(row * 64 + ((ch ^ ((row >> 1) & 3)) << 4));
}

// ======================= GEMM ==============================================
// CTA tile (64*MTILES) x 128, BK=32 halves, 256 threads, 8 warps (4Mx2N),
// warp tile (16*MTILES) x 64. 3-stage cp.async pipeline, swizzled 64B rows.
// MTILES=2 register-capped for 2 CTAs/SM.

template<int MTILES>
__global__ __launch_bounds__(256, (MTILES == 2) ? 2 : 1)
void gemm_hh(const __half* __restrict__ A0, const __half* __restrict__ A1,
             const __half* __restrict__ B0, const __half* __restrict__ B1,
             const float* __restrict__ bias, float* __restrict__ Cf,
             __half* __restrict__ C0, __half* __restrict__ C1,
             float* __restrict__ gsum, float* __restrict__ gssq,
             int M, int N, int Kp, int perm)
{
    constexpr int AROWS   = 64 * MTILES;
    constexpr int OFF_A1_ = AROWS * 64;
    constexpr int OFF_B0_ = 2 * AROWS * 64;
    constexpr int OFF_B1_ = OFF_B0_ + 128 * 64;
    constexpr int STG     = OFF_B0_ + 2 * 128 * 64;

    extern __shared__ char dsm[];
    const uint32_t dynb = smem_u32(dsm);
    const uint32_t base = (dynb + 1023u) & ~1023u;
    char* smg = dsm + (base - dynb);

    const int tid  = threadIdx.x;
    const int wid  = tid >> 5;
    const int lane = tid & 31;
    const int wm   = (wid & 3) * (16 * MTILES);
    const int wn   = (wid >> 2) * 64;
    const int g    = lane >> 2;
    const int t    = lane & 3;
    const int m0   = blockIdx.y * AROWS;
    const int n0   = blockIdx.x * 128;

    const int nk = Kp >> 5;

    auto issue = [&](int k0, uint32_t stg) {
        #pragma unroll
        for (int i = 0; i < MTILES; ++i) {
            const int slot = tid + i * 256;
            const int row = slot >> 2, ch = slot & 3;
            const int gm = m0 + row;
            const int ok = gm < M;
            const long off = (long)(ok ? gm : 0) * Kp + ch * 8 + k0;
            const uint32_t d = swz(row, ch);
            cp16(stg + 0       + d, A0 + off, ok);
            cp16(stg + OFF_A1_ + d, A1 + off, ok);
        }
        #pragma unroll
        for (int i = 0; i < 2; ++i) {
            const int slot = tid + i * 256;
            const int row = slot >> 2, ch = slot & 3;
            const int gn = n0 + row;
            const int ok = gn < N;
            const long off = (long)(ok ? gn : 0) * Kp + ch * 8 + k0;
            const uint32_t d = swz(row, ch);
            cp16(stg + OFF_B0_ + d, B0 + off, ok);
            cp16(stg + OFF_B1_ + d, B1 + off, ok);
        }
        cp_commit();
    };

    float acc[MTILES][8][4];
    #pragma unroll
    for (int a = 0; a < MTILES; a++)
        #pragma unroll
        for (int b = 0; b < 8; b++)
            #pragma unroll
            for (int c = 0; c < 4; c++) acc[a][b][c] = 0.f;

    // 3-stage prologue
    issue(0, base);
    if (nk > 1) issue(32, base + STG);

    for (int it = 0; it < nk; ++it) {
        const uint32_t stg_u = base + (uint32_t)(it % 3) * STG;

        if (it + 2 < nk) {
            issue((it + 2) << 5, base + (uint32_t)((it + 2) % 3) * STG);
            asm volatile("cp.async.wait_group 2;" ::: "memory");
        } else if (it + 1 < nk) {
            asm volatile("cp.async.wait_group 1;" ::: "memory");
        } else {
            asm volatile("cp.async.wait_group 0;" ::: "memory");
        }
        __syncthreads();

        #pragma unroll
        for (int ks = 0; ks < 2; ++ks) {
            uint32_t aH[MTILES][4], aL[MTILES][4];
            {
                const int arw = (lane & 15);
                const int cA  = ks * 2 + (lane >> 4);
                #pragma unroll
                for (int mt = 0; mt < MTILES; ++mt) {
                    const int row = wm + mt * 16 + arw;
                    const uint32_t ad = stg_u + swz(row, cA);
                    ldm4(aH[mt][0], aH[mt][1], aH[mt][2], aH[mt][3], ad + 0);
                    ldm4(aL[mt][0], aL[mt][1], aL[mt][2], aL[mt][3], ad + OFF_A1_);
                }
            }
            const int brw = (lane >> 4) * 8 + (lane & 7);
            const int cB  = ks * 2 + ((lane >> 3) & 1);
            #pragma unroll
            for (int p = 0; p < 4; ++p) {
                uint32_t bH[4], bL[4];
                const int row = wn + p * 16 + brw;
                const uint32_t bd = stg_u + swz(row, cB);
                ldm4(bH[0], bH[1], bH[2], bH[3], bd + OFF_B0_);
                ldm4(bL[0], bL[1], bL[2], bL[3], bd + OFF_B1_);
                #pragma unroll
                for (int sub = 0; sub < 2; ++sub) {
                    const int nt = 2 * p + sub;
                    uint32_t b_h[2] = {bH[sub * 2], bH[sub * 2 + 1]};
                    uint32_t b_l[2] = {bL[sub * 2], bL[sub * 2 + 1]};
                    #pragma unroll
                    for (int mt = 0; mt < MTILES; ++mt) {
                        mma_f16(acc[mt][nt], aH[mt], b_h);
                        mma_f16(acc[mt][nt], aH[mt], b_l);
                        mma_f16(acc[mt][nt], aL[mt], b_h);
                    }
                }
            }
        }
        __syncthreads();
    }

    // ---- epilogue: stores ----
    const bool neven = ((N & 1) == 0);
    #pragma unroll
    for (int mt = 0; mt < MTILES; ++mt) {
        #pragma unroll
        for (int half = 0; half < 2; ++half) {
            const int gm = m0 + wm + mt * 16 + g + half * 8;
            if (gm >= M) continue;
            const int orow = perm ? ((gm & 1023) * 30 + (gm >> 10)) : gm;
            #pragma unroll
            for (int nt = 0; nt < 8; ++nt) {
                const int col = n0 + wn + nt * 8 + t * 2;
                if (col >= N) continue;
                float v0 = acc[mt][nt][half * 2 + 0];
                float v1 = acc[mt][nt][half * 2 + 1];
                if (bias) {
                    v0 += bias[col];
                    if (col + 1 < N) v1 += bias[col + 1];
                }
                if (Cf) {
                    if (neven && col + 1 < N) {
                        *(float2*)&Cf[(long)orow * N + col] = make_float2(v0, v1);
                    } else {
                        Cf[(long)orow * N + col] = v0;
                        if (col + 1 < N) Cf[(long)orow * N + col + 1] = v1;
                    }
                }
                if (C0 && neven && col + 1 < N) {
                    __half h0, l0, h1, l1;
                    f16split(v0, h0, l0);
                    f16split(v1, h1, l1);
                    *(__half2*)&C0[(long)orow * N + col] = __halves2half2(h0, h1);
                    *(__half2*)&C1[(long)orow * N + col] = __halves2half2(l0, l1);
                }
            }
        }
    }

    // ---- fused BN stats (raw accumulators; bias null for these layers) ----
    if (gsum) {
        float* ssum = (float*)smg;        // 128 col sums
        float* ssq2 = ssum + 128;         // 128 col sum-sq
        if (tid < 256) ((float*)smg)[tid] = 0.0f;
        __syncthreads();
        #pragma unroll
        for (int nt = 0; nt < 8; ++nt) {
            #pragma unroll
            for (int j = 0; j < 2; ++j) {
                float s = 0.f, s2 = 0.f;
                #pragma unroll
                for (int mt = 0; mt < MTILES; ++mt) {
                    #pragma unroll
                    for (int half = 0; half < 2; ++half) {
                        const float v = acc[mt][nt][half * 2 + j];
                        s += v; s2 += v * v;
                    }
                }
                #pragma unroll
                for (int o = 16; o >= 4; o >>= 1) {
                    s  += __shfl_down_sync(0xffffffffu, s,  o);
                    s2 += __shfl_down_sync(0xffffffffu, s2, o);
                }
                if (g == 0) {
                    const int cl = wn + nt * 8 + t * 2 + j;
                    atomicAdd(&ssum[cl], s);
                    atomicAdd(&ssq2[cl], s2);
                }
            }
        }
        __syncthreads();
        if (tid < 128 && n0 + tid < N) {
            atomicAdd(&gsum[(n0 + tid) & 511], ssum[tid]);
            atomicAdd(&gssq[(n0 + tid) & 511], ssq2[tid]);
        }
    }
}

constexpr int DS2 = 3 * (2 * 128 * 64 + 2 * 128 * 64) + 1024;   // 99328
constexpr int DS1 = 3 * (2 * 64 * 64 + 2 * 128 * 64) + 1024;    // 74752

// ======================= single prep kernel ================================
__global__ void prep_all(const float* __restrict__ w_e1, const float* __restrict__ w_e2,
                         const float* __restrict__ w_e3, const float* __restrict__ w_d1,
                         const float* __restrict__ w_d2, const float* __restrict__ w_d3,
                         const float* __restrict__ W_in, const float* __restrict__ W_q,
                         const float* __restrict__ W_out, const float* __restrict__ cb,
                         const float* __restrict__ input,
                         __half* hb, float* cn, float* stats, float* loss, int* cnt)
{
    const int  job = blockIdx.y;
    const long tid0 = (long)blockIdx.x * blockDim.x + threadIdx.x;
    const long strd = (long)gridDim.x * blockDim.x;

    auto enc = [&](const float* w, __half* h0, __half* h1, int Kk, int Kp) {
        const int I = 512, Ke = I * Kk;
        const long n = 512L * Kp;
        for (long j = tid0; j < n; j += strd) {
            const int o  = (int)(j / Kp);
            const int kk = (int)(j % Kp);
            float x = 0.f;
            if (kk < Ke) x = w[(long)o * Ke + (long)(kk % I) * Kk + (kk / I)];
            __half h, l; f16split(x, h, l);
            h0[j] = h; h1[j] = l;
        }
    };
    auto dec = [&](const float* w, __half* h0, __half* h1, int Kk) {
        const int I = 512, O = 512;
        const long n = (long)Kk * O * I;
        for (long j = tid0; j < n; j += strd) {
            const int i  = (int)(j % I);
            const int nn = (int)(j / I);
            const int o  = nn % O;
            const int k  = nn / O;
            const float x = w[(long)i * O * Kk + (long)o * Kk + k];
            __half h, l; f16split(x, h, l);
            h0[j] = h; h1[j] = l;
        }
    };
    auto tr = [&](const float* in, __half* h0, __half* h1, int R, int C, int Kp) {
        const long n = (long)C * Kp;
        for (long j = tid0; j < n; j += strd) {
            const int c = (int)(j / Kp);
            const int r = (int)(j % Kp);
            const float x = (r < R) ? in[(long)r * C + c] : 0.f;
            __half h, l; f16split(x, h, l);
            h0[j] = h; h1[j] = l;
        }
    };

    switch (job) {
    case 0: enc(w_e1, hb + H_WE1, hb + H_WE1 + 512L * 2560, 5, 2560); break;
    case 1: enc(w_e2, hb + H_WE2, hb + H_WE2 + 512L * 1536, 3, 1536); break;
    case 2: enc(w_e3, hb + H_WE3, hb + H_WE3 + 512L * 1024, 2, 1024); break;
    case 3: dec(w_d1, hb + H_WD1, hb + H_WD1 + 1024L * 512, 2); break;
    case 4: dec(w_d2, hb + H_WD2, hb + H_WD2 + 1536L * 512, 3); break;
    case 5: dec(w_d3, hb + H_WD3, hb + H_WD3 + 2560L * 512, 5); break;
    case 6: tr(W_in,  hb + H_WIT, hb + H_WIT + 512L * 160, 135, 512, 160); break;
    case 7: tr(W_q,   hb + H_WQT, hb + H_WQT + 512L * 512, 512, 512, 512); break;
    case 8: tr(W_out, hb + H_WOT, hb + H_WOT + 135L * 512, 512, 135, 512); break;
    case 9: {
        __half* h0 = hb + H_CB; __half* h1 = h0 + 512L * 512;
        for (long j = tid0; j < 512L * 512; j += strd) {
            __half h, l; f16split(cb[j], h, l);
            h0[j] = h; h1[j] = l;
        }
        break;
    }
    case 10: {
        __half* h0 = hb + H_XIN; __half* h1 = h0 + 30720L * 160;
        const long n = 30720L * 160;
        for (long j = tid0; j < n; j += strd) {
            const long r = j / 160;
            const int  c = (int)(j % 160);
            const float x = (c < 135) ? input[r * 135 + c] : 0.f;
            __half h, l; f16split(x, h, l);
            h0[j] = h; h1[j] = l;
        }
        break;
    }
    case 11: {
        for (long j = tid0; j < 6L * 2 * 512; j += strd) stats[j] = 0.0f;
        for (long j = tid0; j < 512; j += strd) cnt[j] = 0;
        if (tid0 == 0) loss[0] = 0.0f;
        for (long k = tid0; k < 512; k += strd) {
            float s = 0.f;
            for (int d = 0; d < 512; ++d) {
                const float v = cb[k * 512 + d];
                s += v * v;
            }
            cn[k] = s;
        }
        break;
    }
    }
}

// ======================= BN normalize (+ReLU), 4-wide, smem LUT =============
__global__ void bn_norm2(const float* __restrict__ X,
                         const float* __restrict__ gamma, const float* __restrict__ beta,
                         const float* __restrict__ gsum, const float* __restrict__ gssq,
                         int M, __half* __restrict__ h0, __half* __restrict__ h1,
                         float* __restrict__ fout)
{
    __shared__ float s_scale[512], s_shift[512];
    const float invM = 1.0f / (float)M;
    for (int c = threadIdx.x; c < 512; c += blockDim.x) {
        const float mn = gsum[c] * invM;
        const float vr = gssq[c] * invM - mn * mn;
        const float sc = rsqrtf(vr + EPSV) * gamma[c];
        s_scale[c] = sc;
        s_shift[c] = beta[c] - mn * sc;
    }
    __syncthreads();

    const int total4 = (M * 512) >> 2;
    for (int i4 = blockIdx.x * blockDim.x + threadIdx.x; i4 < total4;
         i4 += gridDim.x * blockDim.x) {
        const long i = (long)i4 << 2;
        const int c0 = (int)(i & 511);
        const float4 x = *(const float4*)&X[i];
        float v[4] = {x.x, x.y, x.z, x.w};
        __half hh[4], ll[4];
        #pragma unroll
        for (int j = 0; j < 4; ++j) {
            float y = fmaf(v[j], s_scale[c0 + j], s_shift[c0 + j]);
            y = y > 0.0f ? y : 0.0f;
            v[j] = y;
            f16split(y, hh[j], ll[j]);
        }
        *(__half2*)&h0[i]     = __halves2half2(hh[0], hh[1]);
        *(__half2*)&h0[i + 2] = __halves2half2(hh[2], hh[3]);
        *(__half2*)&h1[i]     = __halves2half2(ll[0], ll[1]);
        *(__half2*)&h1[i + 2] = __halves2half2(ll[2], ll[3]);
        if (fout) *(float4*)&fout[i] = make_float4(v[0], v[1], v[2], v[3]);
    }
}

// ======================= vector quantization ================================
__global__ void vq_argmin(const float* __restrict__ scores, const float* __restrict__ cnorm,
                          const float* __restrict__ cb,
                          const __half* __restrict__ cb0, const __half* __restrict__ cb1,
                          const float* __restrict__ z,
                          float* __restrict__ q, __half* __restrict__ qh,
                          __half* __restrict__ ql,
                          int* __restrict__ counts, float* __restrict__ loss)
{
    const int n = blockIdx.x;
    const int k = threadIdx.x;
    const float d = cnorm[k] - 2.0f * scores[(long)n * 512 + k];
    __shared__ float sv[512];
    __shared__ int   si[512];
    sv[k] = d; si[k] = k;
    __syncthreads();
    for (int st = 256; st > 0; st >>= 1) {
        if (k < st) {
            const float ov = sv[k + st];
            const int   oi = si[k + st];
            if (ov < sv[k] || (ov == sv[k] && oi < si[k])) { sv[k] = ov; si[k] = oi; }
        }
        __syncthreads();
    }
    const int best = si[0];
    __syncthreads();

    const float val = cb[(long)best * 512 + k];
    q [(long)n * 512 + k] = val;
    qh[(long)n * 512 + k] = cb0[(long)best * 512 + k];
    ql[(long)n * 512 + k] = cb1[(long)best * 512 + k];

    const float diff = val - z[(long)n * 512 + k];
    sv[k] = diff * diff;
    __syncthreads();
    for (int st = 256; st > 0; st >>= 1) {
        if (k < st) sv[k] += sv[k + st];
        __syncthreads();
    }
    if (k == 0) {
        atomicAdd(&counts[best], 1);
        atomicAdd(loss, sv[0]);
    }
}

__global__ void finalize_k(const int* __restrict__ counts, const float* __restrict__ loss,
                           float* __restrict__ out, long outsize)
{
    const int k = threadIdx.x;
    const float p = (float)counts[k] * (1.0f / 1024.0f);
    __shared__ float sh[512];
    sh[k] = p * logf(p + 1e-10f);
    __syncthreads();
    for (int st = 256; st > 0; st >>= 1) {
        if (k < st) sh[k] += sh[k + st];
        __syncthreads();
    }
    if (k == 0) {
        const long R = 1024L * 30 * 135;
        if (outsize >= R + 2) {
            out[R]     = loss[0] * 1.25f / (1024.0f * 512.0f);
            out[R + 1] = expf(-sh[0]);
        }
    }
}

// ======================= host launch ========================================
static inline dim3 grid128(int M, int N) { return dim3((N + 127) / 128, (M + 127) / 128); }
static inline dim3 grid64(int M, int N)  { return dim3((N + 127) / 128, (M + 63) / 64); }

static void run_bn(const float* X, const float* g, const float* b, int M,
                   float* stats, int layer, __half* h0, __half* h1, float* fout)
{
    float* sum = stats + layer * 1024;
    float* ssq = sum + 512;
    int nb = (M * 512 / 4 + 255) / 256; if (nb > 2048) nb = 2048;
    bn_norm2<<<nb, 256>>>(X, g, b, sum, ssq, M, h0, h1, fout);
}

extern "C" void kernel_launch(void* const* d_in, const int* in_sizes, int n_in,
                              void* d_out, int out_size)
{
    (void)in_sizes; (void)n_in;
    float* buf = nullptr;
    __half* hb = nullptr;
    cudaGetSymbolAddress((void**)&buf, g_buf);
    cudaGetSymbolAddress((void**)&hb, g_hbuf);
    cudaFuncSetAttribute(gemm_hh<2>, cudaFuncAttributeMaxDynamicSharedMemorySize, DS2);
    cudaFuncSetAttribute(gemm_hh<1>, cudaFuncAttributeMaxDynamicSharedMemorySize, DS1);

    const float* input = (const float*)d_in[0];
    const float* W_in  = (const float*)d_in[1];
    const float* b_in  = (const float*)d_in[2];
    const float* w_e1  = (const float*)d_in[3];
    const float* g_e1  = (const float*)d_in[4];
    const float* b_e1  = (const float*)d_in[5];
    const float* w_e2  = (const float*)d_in[6];
    const float* g_e2  = (const float*)d_in[7];
    const float* b_e2  = (const float*)d_in[8];
    const float* w_e3  = (const float*)d_in[9];
    const float* g_e3  = (const float*)d_in[10];
    const float* b_e3  = (const float*)d_in[11];
    const float* cb    = (const float*)d_in[12];
    const float* W_q   = (const float*)d_in[13];
    const float* b_q   = (const float*)d_in[14];
    const float* w_d1  = (const float*)d_in[15];
    const float* g_d1  = (const float*)d_in[16];
    const float* b_d1  = (const float*)d_in[17];
    const float* w_d2  = (const float*)d_in[18];
    const float* g_d2  = (const float*)d_in[19];
    const float* b_d2  = (const float*)d_in[20];
    const float* w_d3  = (const float*)d_in[21];
    const float* g_d3  = (const float*)d_in[22];
    const float* b_d3  = (const float*)d_in[23];
    const float* W_out = (const float*)d_in[24];
    const float* b_out = (const float*)d_in[25];

    float* e1r  = buf + O_E1R;
    float* e2r  = buf + O_E2R;
    float* zr   = buf + O_ZR;
    float* z    = buf + O_Z;
    float* q    = buf + O_Q;
    float* d1r  = buf + O_D1R;
    float* d2r  = buf + O_D2R;
    float* d3r  = buf + O_D3R;
    float* sc   = buf + O_SC;
    float* cn   = buf + O_CN;
    float* stats= buf + O_STAT;
    float* loss = buf + O_LOSS;
    int*   cnt  = (int*)(buf + O_CNT);

    __half* we1_0 = hb + H_WE1; __half* we1_1 = we1_0 + 512L * 2560;
    __half* we2_0 = hb + H_WE2; __half* we2_1 = we2_0 + 512L * 1536;
    __half* we3_0 = hb + H_WE3; __half* we3_1 = we3_0 + 512L * 1024;
    __half* wd1_0 = hb + H_WD1; __half* wd1_1 = wd1_0 + 1024L * 512;
    __half* wd2_0 = hb + H_WD2; __half* wd2_1 = wd2_0 + 1536L * 512;
    __half* wd3_0 = hb + H_WD3; __half* wd3_1 = wd3_0 + 2560L * 512;
    __half* wit_0 = hb + H_WIT; __half* wit_1 = wit_0 + 512L * 160;
    __half* wqt_0 = hb + H_WQT; __half* wqt_1 = wqt_0 + 512L * 512;
    __half* wot_0 = hb + H_WOT; __half* wot_1 = wot_0 + 135L * 512;
    __half* cb_0  = hb + H_CB;  __half* cb_1  = cb_0  + 512L * 512;
    __half* xin_0 = hb + H_XIN; __half* xin_1 = xin_0 + 30720L * 160;
    __half* x0_0  = hb + H_X0;  __half* x0_1  = x0_0  + 30720L * 512;
    __half* e1_0  = hb + H_E1;  __half* e1_1  = e1_0  + 6144L * 512;
    __half* e2_0  = hb + H_E2;  __half* e2_1  = e2_0  + 2048L * 512;
    __half* z_0   = hb + H_Z;   __half* z_1   = z_0   + 1024L * 512;
    __half* q_0   = hb + H_Q;   __half* q_1   = q_0   + 1024L * 512;
    __half* d0_0  = hb + H_D0;  __half* d0_1  = d0_0  + 1024L * 512;
    __half* d1_0  = hb + H_D1;  __half* d1_1  = d1_0  + 1024L * 1024;
    __half* d2_0  = hb + H_D2;  __half* d2_1  = d2_0  + 2048L * 1536;
    __half* d3_0  = hb + H_D3;  __half* d3_1  = d3_0  + 30720L * 512;

    float* out = (float*)d_out;

    // ---- prep: everything in ONE launch ----
    prep_all<<<dim3(160, 12), 256>>>(w_e1, w_e2, w_e3, w_d1, w_d2, w_d3,
                                     W_in, W_q, W_out, cb, input,
                                     hb, cn, stats, loss, cnt);

    float* st0 = stats;
    float* st1 = stats + 1024;
    float* st2 = stats + 2048;
    float* st3 = stats + 3072;
    float* st4 = stats + 4096;
    float* st5 = stats + 5120;

    // ---- input GEMM: K=135(pad160) -> 512, split-only out, perm ----
    gemm_hh<2><<<grid128(30720, 512), 256, DS2>>>(
        xin_0, xin_1, wit_0, wit_1, b_in, nullptr, x0_0, x0_1,
        nullptr, nullptr, 30720, 512, 160, 1);

    // ---- encoder (stats fused into GEMM epilogues) ----
    gemm_hh<2><<<grid128(6144, 512), 256, DS2>>>(
        x0_0, x0_1, we1_0, we1_1, nullptr, e1r, nullptr, nullptr,
        st0, st0 + 512, 6144, 512, 2560, 0);
    run_bn(e1r, g_e1, b_e1, 6144, stats, 0, e1_0, e1_1, nullptr);

    gemm_hh<1><<<grid64(2048, 512), 256, DS1>>>(
        e1_0, e1_1, we2_0, we2_1, nullptr, e2r, nullptr, nullptr,
        st1, st1 + 512, 2048, 512, 1536, 0);
    run_bn(e2r, g_e2, b_e2, 2048, stats, 1, e2_0, e2_1, nullptr);

    gemm_hh<1><<<grid64(1024, 512), 256, DS1>>>(
        e2_0, e2_1, we3_0, we3_1, nullptr, zr, nullptr, nullptr,
        st2, st2 + 512, 1024, 512, 1024, 0);
    run_bn(zr, g_e3, b_e3, 1024, stats, 2, z_0, z_1, z);

    // ---- vector quantization ----
    gemm_hh<1><<<grid64(1024, 512), 256, DS1>>>(
        z_0, z_1, cb_0, cb_1, nullptr, sc, nullptr, nullptr,
        nullptr, nullptr, 1024, 512, 512, 0);
    vq_argmin<<<1024, 512>>>(sc, cn, cb, cb_0, cb_1, z, q, q_0, q_1, cnt, loss);

    // ---- decoder ----
    gemm_hh<1><<<grid64(1024, 512), 256, DS1>>>(
        q_0, q_1, wqt_0, wqt_1, b_q, nullptr, d0_0, d0_1,
        nullptr, nullptr, 1024, 512, 512, 0);

    gemm_hh<1><<<grid64(1024, 1024), 256, DS1>>>(
        d0_0, d0_1, wd1_0, wd1_1, nullptr, d1r, nullptr, nullptr,
        st3, st3 + 512, 1024, 1024, 512, 0);
    run_bn(d1r, g_d1, b_d1, 2048, stats, 3, d1_0, d1_1, nullptr);

    gemm_hh<2><<<grid128(2048, 1536), 256, DS2>>>(
        d1_0, d1_1, wd2_0, wd2_1, nullptr, d2r, nullptr, nullptr,
        st4, st4 + 512, 2048, 1536, 512, 0);
    run_bn(d2r, g_d2, b_d2, 6144, stats, 4, d2_0, d2_1, nullptr);

    gemm_hh<2><<<grid128(6144, 2560), 256, DS2>>>(
        d2_0, d2_1, wd3_0, wd3_1, nullptr, d3r, nullptr, nullptr,
        st5, st5 + 512, 6144, 2560, 512, 0);
    run_bn(d3r, g_d3, b_d3, 30720, stats, 5, d3_0, d3_1, nullptr);

    // ---- output GEMM -> recon ----
    gemm_hh<2><<<grid128(30720, 135), 256, DS2>>>(
        d3_0, d3_1, wot_0, wot_1, b_out, out, nullptr, nullptr,
        nullptr, nullptr, 30720, 135, 512, 0);

    // ---- scalars ----
    finalize_k<<<1, 512>>>(cnt, loss, out, (long)out_size);
}